// round 10
// baseline (speedup 1.0000x reference)
#include <cuda_runtime.h>
#include <cuda_bf16.h>
#include <cstdint>
#include <cstddef>

// ---------------------------------------------------------------------------
// Problem constants
// ---------------------------------------------------------------------------
#define B_   16
#define C_   64
#define T_   30
#define H_   64
#define W_   44
#define SPAT (T_ * H_ * W_)        // 84480
#define TH_STRIDE (H_ * W_)        // 2816

// conv tiling
#define HH 8                       // output h rows per tile
#define HP 10                      // h rows incl halo
#define WP 48                      // padded w per row
#define ROWS (3 * HP * WP)         // 1440 pixel rows per slab
#define ROWSP 1456                 // padded rows (ldmatrix tap-shift bleed)
#define SLABB (ROWSP * 32)         // 46592 B per term slab
#define BUFB  (2 * SLABB)          // 93184 B per buffer (xh + xl)
#define SM_TOTAL (2 * BUFB)        // 186368 B

#define NTILES 3840                // 30 t * 8 hq * 16 b
#define GRIDP  148                 // persistent CTAs

#define PR_ROWS (B_ * 4 * T_ * H_ * WP)   // 5,898,240 scratch rows

// Scratch (static device globals; no allocation)
__device__ float d_gap[B_ * C_];
__device__ float d_h[B_ * 128];
// W fragments, mma-lane order: [b][g:4][tap:27][term:2][mt:4][lane:32] uint4
__device__ uint4 d_wfrag[B_ * 4 * 27 * 2 * 4 * 32];
// x hi/lo bf16 scratch, smem-row layout: [b][g][t][h][j:48] rows of 32B (16 ic)
__device__ uint4 d_xh[PR_ROWS * 2];
__device__ uint4 d_xl[PR_ROWS * 2];

// ---------------------------------------------------------------------------
// helpers
// ---------------------------------------------------------------------------
__device__ __forceinline__ unsigned smem_u32(const void* p) {
    unsigned a;
    asm("{ .reg .u64 t; cvta.to.shared.u64 t, %1; cvt.u32.u64 %0, t; }"
        : "=r"(a) : "l"(p));
    return a;
}
__device__ __forceinline__ void ldmx4(unsigned& r0, unsigned& r1,
                                      unsigned& r2, unsigned& r3, unsigned a) {
    asm volatile("ldmatrix.sync.aligned.m8n8.x4.shared.b16 {%0,%1,%2,%3}, [%4];"
                 : "=r"(r0), "=r"(r1), "=r"(r2), "=r"(r3) : "r"(a));
}
__device__ __forceinline__ void mma_bf16(float* c, const uint4 a,
                                         unsigned b0, unsigned b1) {
    asm volatile(
        "mma.sync.aligned.m16n8k16.row.col.f32.bf16.bf16.f32 "
        "{%0,%1,%2,%3}, {%4,%5,%6,%7}, {%8,%9}, {%0,%1,%2,%3};"
        : "+f"(c[0]), "+f"(c[1]), "+f"(c[2]), "+f"(c[3])
        : "r"(a.x), "r"(a.y), "r"(a.z), "r"(a.w), "r"(b0), "r"(b1));
}
__device__ __forceinline__ unsigned bf_hi(float v) {
    return (unsigned)__bfloat16_as_ushort(__float2bfloat16_rn(v));
}
__device__ __forceinline__ unsigned bf_lo(float v) {
    float hf = __bfloat162float(__float2bfloat16_rn(v));
    return (unsigned)__bfloat16_as_ushort(__float2bfloat16_rn(v - hf));
}
__device__ __forceinline__ void cp16(unsigned dst, const void* src, unsigned sz) {
    asm volatile("cp.async.cg.shared.global [%0], [%1], 16, %2;"
                 :: "r"(dst), "l"(src), "r"(sz) : "memory");
}
__device__ __forceinline__ void cp_commit() {
    asm volatile("cp.async.commit_group;" ::: "memory");
}
__device__ __forceinline__ void cp_wait0() {
    asm volatile("cp.async.wait_group 0;" ::: "memory");
}

// ---------------------------------------------------------------------------
// Kernel 1: global average pool. 1024 blocks.
// ---------------------------------------------------------------------------
__global__ void gap_kernel(const float* __restrict__ x) {
    const int bc = blockIdx.x;
    const float4* xp = reinterpret_cast<const float4*>(x) + (size_t)bc * (SPAT / 4);
    float s = 0.f;
    for (int i = threadIdx.x; i < SPAT / 4; i += 256) {
        float4 v = xp[i];
        s += (v.x + v.y) + (v.z + v.w);
    }
    #pragma unroll
    for (int o = 16; o > 0; o >>= 1) s += __shfl_xor_sync(0xffffffffu, s, o);
    __shared__ float red[8];
    if ((threadIdx.x & 31) == 0) red[threadIdx.x >> 5] = s;
    __syncthreads();
    if (threadIdx.x < 8) {
        float v = red[threadIdx.x];
        #pragma unroll
        for (int o = 4; o > 0; o >>= 1) v += __shfl_xor_sync(0xffu, v, o);
        if (threadIdx.x == 0) d_gap[bc] = v * (1.0f / (float)SPAT);
    }
}

// ---------------------------------------------------------------------------
// Kernel 2: reduce FC + fc1 + sigmoid. Single block.
// ---------------------------------------------------------------------------
__global__ void fc_kernel(const float* __restrict__ w_reduce,
                          const float* __restrict__ b_reduce,
                          const float* __restrict__ w_fc1,
                          const float* __restrict__ b_fc1) {
    __shared__ float sg[B_ * 16];
    const int tid = threadIdx.x;
    if (tid < B_ * 16) {
        int b = tid >> 4, j = tid & 15;
        float s = b_reduce[j];
        #pragma unroll 4
        for (int i = 0; i < 64; i++) s += d_gap[b * 64 + i] * w_reduce[j * 64 + i];
        sg[b * 16 + j] = s;
    }
    __syncthreads();
    for (int idx = tid; idx < B_ * 128; idx += 256) {
        int b = idx >> 7, c = idx & 127;
        float s = b_fc1[c];
        #pragma unroll
        for (int i = 0; i < 16; i++) s += sg[b * 16 + i] * w_fc1[c * 16 + i];
        d_h[idx] = 1.0f / (1.0f + expf(-s));
    }
}

// ---------------------------------------------------------------------------
// Kernel 3: dynamic weights -> mma a-fragment layout (hi and lo terms).
// ---------------------------------------------------------------------------
__global__ void wdyn_kernel(const float* __restrict__ w_fc2) {
    const int idx = blockIdx.x * blockDim.x + threadIdx.x;
    const int total = B_ * 4 * 27 * 2 * 4 * 32;   // 442368
    if (idx >= total) return;
    const int lane = idx & 31;
    const int mt   = (idx >> 5) & 3;
    const int term = (idx >> 7) & 1;
    int q = idx >> 8;
    const int tap = q % 27;  q /= 27;
    const int g   = q & 3;
    const int b   = q >> 2;

    unsigned r32[4];
    #pragma unroll
    for (int r = 0; r < 4; r++) {
        const int row = (lane >> 2) + (r & 1) * 8;
        const int kb  = 2 * (lane & 3) + (r >> 1) * 8;
        const int oc  = mt * 16 + row;
        unsigned e[2];
        #pragma unroll
        for (int j = 0; j < 2; j++) {
            const int ic = g * 16 + kb + j;
            const float v = w_fc2[oc * 1728 + ic * 27 + tap] *
                            d_h[b * 128 + oc * 2 + (ic >= 32 ? 1 : 0)];
            e[j] = term == 0 ? bf_hi(v) : bf_lo(v);
        }
        r32[r] = e[0] | (e[1] << 16);
    }
    d_wfrag[idx] = make_uint4(r32[0], r32[1], r32[2], r32[3]);
}

// ---------------------------------------------------------------------------
// Kernel 3b: x pre-pass (f32 -> bf16 hi/lo, smem-row layout, halo pre-zeroed).
// ---------------------------------------------------------------------------
__global__ void prepass_kernel(const float* __restrict__ x) {
    const int i = blockIdx.x * 256 + threadIdx.x;
    if (i >= PR_ROWS) return;
    int j = i % WP;  int q = i / WP;
    int h = q % H_;  q /= H_;
    int t = q % T_;  q /= T_;
    int g = q & 3;
    int b = q >> 2;

    uint4 h0 = make_uint4(0, 0, 0, 0), h1 = h0, l0 = h0, l1 = h0;
    const int gw = j - 1;
    if ((unsigned)gw < (unsigned)W_) {
        const float* p = x + ((size_t)(b * C_ + g * 16) * T_ + t) * TH_STRIDE +
                         h * W_ + gw;
        unsigned hh[8], ll[8];
        #pragma unroll
        for (int k = 0; k < 8; k++) {
            float v0 = __ldg(p + (size_t)(2 * k) * SPAT);
            float v1 = __ldg(p + (size_t)(2 * k + 1) * SPAT);
            hh[k] = bf_hi(v0) | (bf_hi(v1) << 16);
            ll[k] = bf_lo(v0) | (bf_lo(v1) << 16);
        }
        h0 = make_uint4(hh[0], hh[1], hh[2], hh[3]);
        h1 = make_uint4(hh[4], hh[5], hh[6], hh[7]);
        l0 = make_uint4(ll[0], ll[1], ll[2], ll[3]);
        l1 = make_uint4(ll[4], ll[5], ll[6], ll[7]);
    }
    d_xh[(size_t)i * 2]     = h0;
    d_xh[(size_t)i * 2 + 1] = h1;
    d_xl[(size_t)i * 2]     = l0;
    d_xl[(size_t)i * 2 + 1] = l1;
}

// ---------------------------------------------------------------------------
// Kernel 4: persistent implicit-GEMM conv (mma.sync bf16, 3-term hi/lo).
// 148 CTAs; each walks its tiles as one flattened (tile, g) stage stream with
// cp.async double-buffering across ALL stage boundaries (incl. tile->tile).
// W frags pipelined one tap ahead; bh frags pipelined one tap ahead.
// ---------------------------------------------------------------------------
extern __shared__ char smem[];

__global__ void __launch_bounds__(256, 1)
conv_kernel(float* __restrict__ out) {
    const int p = blockIdx.x;
    if (p >= NTILES) return;
    const int ntiles_mine = (NTILES - p + GRIDP - 1) / GRIDP;

    const int tid = threadIdx.x;
    const int wid = tid >> 5;
    const int lane = tid & 31;
    const unsigned sb = smem_u32(smem);

    const int rb_off = (lane & 7) + ((lane >> 4) & 1) * 8;
    const int bhalf  = (lane >> 3) & 1;

    auto coords = [](int tt, int& b, int& t, int& h0) {
        b = tt / 240;
        int r = tt - b * 240;
        t = r >> 3;
        h0 = (r & 7) * 8;
    };

    // ---- stage prefetch: fill buffer `buf` for (b,t,h0,g) via zfill cp.async
    auto prefetch = [&](int b, int t, int h0, int g, int buf) {
        const char* xh8 = reinterpret_cast<const char*>(d_xh);
        const char* xl8 = reinterpret_cast<const char*>(d_xl);
        #pragma unroll 1
        for (int i = tid; i < 2 * ROWS * 2; i += 256) {
            const int term = i >= 2 * ROWS;
            const int rem  = term ? i - 2 * ROWS : i;
            const int r  = rem >> 1;
            const int hb = rem & 1;
            int t2 = r / (HP * WP);
            int rr = r - t2 * (HP * WP);
            int hp = rr / WP;
            int wp = rr - hp * WP;
            const int gt = t + t2 - 1, gh = h0 + hp - 1;
            const unsigned ok =
                (((unsigned)gt < (unsigned)T_) & ((unsigned)gh < (unsigned)H_))
                ? 16u : 0u;
            const int gtc = gt < 0 ? 0 : (gt >= T_ ? T_ - 1 : gt);
            const int ghc = gh < 0 ? 0 : (gh >= H_ ? H_ - 1 : gh);
            const size_t srow =
                ((((size_t)(b * 4 + g) * T_ + gtc) * H_ + ghc) * WP + wp);
            const char* src = (term ? xl8 : xh8) + srow * 32 + hb * 16;
            const unsigned dst = sb + buf * BUFB + term * SLABB + r * 32 +
                                 ((((r >> 2) & 1) ^ hb) << 4);
            cp16(dst, src, ok);
        }
        cp_commit();
    };

    float acc[4][6][4];
    #pragma unroll
    for (int mt = 0; mt < 4; mt++)
        #pragma unroll
        for (int nt = 0; nt < 6; nt++)
            #pragma unroll
            for (int k = 0; k < 4; k++) acc[mt][nt][k] = 0.f;

    int tt = p, b, t, h0;
    coords(tt, b, t, h0);
    prefetch(b, t, h0, 0, 0);

    // preload W frags for (b, g=0, tap=0)
    uint4 whc[4], wlc[4];
    {
        const uint4* wt = d_wfrag + (size_t)(b * 4) * 27 * 256 + lane;
        #pragma unroll
        for (int mt = 0; mt < 4; mt++) {
            whc[mt] = __ldg(wt + mt * 32);
            wlc[mt] = __ldg(wt + 128 + mt * 32);
        }
    }

    int buf = 0;
    #pragma unroll 1
    for (int ti = 0; ti < ntiles_mine; ti++) {
        const bool last_tile = (ti == ntiles_mine - 1);
        int nb = b, nt_ = t, nh0 = h0;
        if (!last_tile) coords(tt + GRIDP, nb, nt_, nh0);

        #pragma unroll 1
        for (int g = 0; g < 4; g++) {
            cp_wait0();
            __syncthreads();
            // issue next-stage fill (crosses tile boundary at g==3)
            if (g < 3)            prefetch(b, t, h0, g + 1, buf ^ 1);
            else if (!last_tile)  prefetch(nb, nt_, nh0, 0, buf ^ 1);

            const unsigned sl_h = sb + buf * BUFB;
            const unsigned sl_l = sl_h + SLABB;

            const uint4* wf_cur = d_wfrag + (size_t)((b * 4 + g) * 27) * 256 + lane;
            const uint4* wf_next =
                (g < 3) ? wf_cur + 27 * 256
                        : (!last_tile ? d_wfrag + (size_t)(nb * 4) * 27 * 256 + lane
                                      : wf_cur + 26 * 256);   // clamp at very end

            // preload bh for tap 0 (shift = 0)
            unsigned bhc[12];
            #pragma unroll
            for (int q = 0; q < 3; q++) {
                int r = wid * 48 + q * 16 + rb_off;
                unsigned a = r * 32 + (((((r >> 2) & 1) ^ bhalf)) << 4);
                ldmx4(bhc[q * 4], bhc[q * 4 + 1], bhc[q * 4 + 2], bhc[q * 4 + 3],
                      sl_h + a);
            }

            #pragma unroll 1
            for (int tap = 0; tap < 27; tap++) {
                const int dt2 = tap / 9;
                const int rem = tap - dt2 * 9;
                const int dh  = rem / 3;
                const int dw  = rem - dh * 3;
                const int shift = (dt2 * HP + dh) * WP + dw;

                // ldmatrix: bl for current tap
                unsigned bl[12];
                #pragma unroll
                for (int q = 0; q < 3; q++) {
                    int r = wid * 48 + q * 16 + rb_off + shift;
                    unsigned a = r * 32 + (((((r >> 2) & 1) ^ bhalf)) << 4);
                    ldmx4(bl[q * 4], bl[q * 4 + 1], bl[q * 4 + 2], bl[q * 4 + 3],
                          sl_l + a);
                }
                // ldmatrix: bh for next tap (within this stage)
                unsigned bhn[12];
                if (tap < 26) {
                    const int tap1 = tap + 1;
                    const int dt2n = tap1 / 9;
                    const int remn = tap1 - dt2n * 9;
                    const int shn = (dt2n * HP + remn / 3) * WP + (remn % 3);
                    #pragma unroll
                    for (int q = 0; q < 3; q++) {
                        int r = wid * 48 + q * 16 + rb_off + shn;
                        unsigned a = r * 32 + (((((r >> 2) & 1) ^ bhalf)) << 4);
                        ldmx4(bhn[q * 4], bhn[q * 4 + 1], bhn[q * 4 + 2],
                              bhn[q * 4 + 3], sl_h + a);
                    }
                }
                // W prefetch for next tap / next stage
                const uint4* wt = (tap < 26) ? wf_cur + (size_t)(tap + 1) * 256
                                             : wf_next;
                uint4 whn[4], wln[4];
                #pragma unroll
                for (int mt = 0; mt < 4; mt++) {
                    whn[mt] = __ldg(wt + mt * 32);
                    wln[mt] = __ldg(wt + 128 + mt * 32);
                }

                // mma group 1: wh * bh (operands already resident)
                #pragma unroll
                for (int mt = 0; mt < 4; mt++)
                    #pragma unroll
                    for (int nt = 0; nt < 6; nt++) {
                        const int q = nt >> 1, pr = (nt & 1) * 2;
                        mma_bf16(acc[mt][nt], whc[mt],
                                 bhc[q * 4 + pr], bhc[q * 4 + pr + 1]);
                    }
                // mma group 2: wh * bl
                #pragma unroll
                for (int mt = 0; mt < 4; mt++)
                    #pragma unroll
                    for (int nt = 0; nt < 6; nt++) {
                        const int q = nt >> 1, pr = (nt & 1) * 2;
                        mma_bf16(acc[mt][nt], whc[mt],
                                 bl[q * 4 + pr], bl[q * 4 + pr + 1]);
                    }
                // mma group 3: wl * bh
                #pragma unroll
                for (int mt = 0; mt < 4; mt++)
                    #pragma unroll
                    for (int nt = 0; nt < 6; nt++) {
                        const int q = nt >> 1, pr = (nt & 1) * 2;
                        mma_bf16(acc[mt][nt], wlc[mt],
                                 bhc[q * 4 + pr], bhc[q * 4 + pr + 1]);
                    }

                // rotate pipelines
                #pragma unroll
                for (int mt = 0; mt < 4; mt++) { whc[mt] = whn[mt]; wlc[mt] = wln[mt]; }
                if (tap < 26) {
                    #pragma unroll
                    for (int k = 0; k < 12; k++) bhc[k] = bhn[k];
                }
            }
            buf ^= 1;
        }

        // ---- epilogue for this tile ----
        {
            const int gh = h0 + wid;
            #pragma unroll
            for (int mt = 0; mt < 4; mt++) {
                const int oc0 = mt * 16 + (lane >> 2);
                #pragma unroll
                for (int nt = 0; nt < 6; nt++) {
                    const int wc = nt * 8 + 2 * (lane & 3);
                    if (wc < W_) {
                        size_t o0 = ((size_t)(b * C_ + oc0) * T_ + t) * TH_STRIDE +
                                    gh * W_ + wc;
                        size_t o1 = o0 + (size_t)8 * SPAT;
                        *(float2*)(out + o0) =
                            make_float2(acc[mt][nt][0], acc[mt][nt][1]);
                        *(float2*)(out + o1) =
                            make_float2(acc[mt][nt][2], acc[mt][nt][3]);
                    }
                    #pragma unroll
                    for (int k = 0; k < 4; k++) acc[mt][nt][k] = 0.f;
                }
            }
        }

        tt += GRIDP; b = nb; t = nt_; h0 = nh0;
    }
}

// ---------------------------------------------------------------------------
extern "C" void kernel_launch(void* const* d_in, const int* in_sizes, int n_in,
                              void* d_out, int out_size) {
    const float* x        = (const float*)d_in[0];
    const float* w_reduce = (const float*)d_in[1];
    const float* b_reduce = (const float*)d_in[2];
    const float* w_fc1    = (const float*)d_in[3];
    const float* b_fc1    = (const float*)d_in[4];
    const float* w_fc2    = (const float*)d_in[5];
    float* out = (float*)d_out;

    cudaFuncSetAttribute(conv_kernel,
                         cudaFuncAttributeMaxDynamicSharedMemorySize, SM_TOTAL);

    gap_kernel<<<B_ * C_, 256>>>(x);
    fc_kernel<<<1, 256>>>(w_reduce, b_reduce, w_fc1, b_fc1);
    {
        const int total = B_ * 4 * 27 * 2 * 4 * 32;
        wdyn_kernel<<<(total + 255) / 256, 256>>>(w_fc2);
    }
    prepass_kernel<<<(PR_ROWS + 255) / 256, 256>>>(x);
    conv_kernel<<<GRIDP, 256, SM_TOTAL>>>(out);
}

// round 12
// speedup vs baseline: 1.0784x; 1.0784x over previous
#include <cuda_runtime.h>
#include <cuda_bf16.h>
#include <cstdint>
#include <cstddef>

// ---------------------------------------------------------------------------
// Problem constants
// ---------------------------------------------------------------------------
#define B_   16
#define C_   64
#define T_   30
#define H_   64
#define W_   44
#define SPAT (T_ * H_ * W_)        // 84480
#define TH_STRIDE (H_ * W_)        // 2816

// conv tiling
#define HH 8                       // output h rows per tile
#define HP 10                      // h rows incl halo
#define WP 48                      // padded w per row
#define ROWS (3 * HP * WP)         // 1440 pixel rows per slab
#define ROWSP 1456                 // padded rows (ldmatrix tap-shift bleed)
#define SLABB (ROWSP * 32)         // 46592 B per term slab
#define BUFB  (2 * SLABB)          // 93184 B per buffer (xh + xl)
#define SM_TOTAL (2 * BUFB)        // 186368 B

#define NTILES 3840                // 30 t * 8 hq * 16 b
#define GRIDP  148                 // persistent CTAs

#define PR_ROWS (B_ * 4 * T_ * H_ * WP)   // 5,898,240 scratch rows

// Scratch (static device globals; no allocation)
__device__ float d_gap[B_ * C_];
__device__ float d_h[B_ * 128];
// W fragments, mma-lane order: [b][g:4][tap:27][term:2][mt:4][lane:32] uint4
__device__ uint4 d_wfrag[B_ * 4 * 27 * 2 * 4 * 32];
// x hi/lo bf16 scratch, smem-row layout: [b][g][t][h][j:48] rows of 32B (16 ic)
__device__ uint4 d_xh[PR_ROWS * 2];
__device__ uint4 d_xl[PR_ROWS * 2];

// ---------------------------------------------------------------------------
// helpers
// ---------------------------------------------------------------------------
__device__ __forceinline__ unsigned smem_u32(const void* p) {
    unsigned a;
    asm("{ .reg .u64 t; cvta.to.shared.u64 t, %1; cvt.u32.u64 %0, t; }"
        : "=r"(a) : "l"(p));
    return a;
}
__device__ __forceinline__ void ldmx4(unsigned& r0, unsigned& r1,
                                      unsigned& r2, unsigned& r3, unsigned a) {
    asm volatile("ldmatrix.sync.aligned.m8n8.x4.shared.b16 {%0,%1,%2,%3}, [%4];"
                 : "=r"(r0), "=r"(r1), "=r"(r2), "=r"(r3) : "r"(a));
}
__device__ __forceinline__ void mma_bf16(float* c, const uint4 a,
                                         unsigned b0, unsigned b1) {
    asm volatile(
        "mma.sync.aligned.m16n8k16.row.col.f32.bf16.bf16.f32 "
        "{%0,%1,%2,%3}, {%4,%5,%6,%7}, {%8,%9}, {%0,%1,%2,%3};"
        : "+f"(c[0]), "+f"(c[1]), "+f"(c[2]), "+f"(c[3])
        : "r"(a.x), "r"(a.y), "r"(a.z), "r"(a.w), "r"(b0), "r"(b1));
}
__device__ __forceinline__ unsigned bf_hi(float v) {
    return (unsigned)__bfloat16_as_ushort(__float2bfloat16_rn(v));
}
__device__ __forceinline__ unsigned bf_lo(float v) {
    float hf = __bfloat162float(__float2bfloat16_rn(v));
    return (unsigned)__bfloat16_as_ushort(__float2bfloat16_rn(v - hf));
}
__device__ __forceinline__ void cp16(unsigned dst, const void* src, unsigned sz) {
    asm volatile("cp.async.cg.shared.global [%0], [%1], 16, %2;"
                 :: "r"(dst), "l"(src), "r"(sz) : "memory");
}
__device__ __forceinline__ void cp_commit() {
    asm volatile("cp.async.commit_group;" ::: "memory");
}
__device__ __forceinline__ void cp_wait0() {
    asm volatile("cp.async.wait_group 0;" ::: "memory");
}

// ---------------------------------------------------------------------------
// Kernel 1: global average pool. 1024 blocks.
// ---------------------------------------------------------------------------
__global__ void gap_kernel(const float* __restrict__ x) {
    const int bc = blockIdx.x;
    const float4* xp = reinterpret_cast<const float4*>(x) + (size_t)bc * (SPAT / 4);
    float s = 0.f;
    for (int i = threadIdx.x; i < SPAT / 4; i += 256) {
        float4 v = xp[i];
        s += (v.x + v.y) + (v.z + v.w);
    }
    #pragma unroll
    for (int o = 16; o > 0; o >>= 1) s += __shfl_xor_sync(0xffffffffu, s, o);
    __shared__ float red[8];
    if ((threadIdx.x & 31) == 0) red[threadIdx.x >> 5] = s;
    __syncthreads();
    if (threadIdx.x < 8) {
        float v = red[threadIdx.x];
        #pragma unroll
        for (int o = 4; o > 0; o >>= 1) v += __shfl_xor_sync(0xffu, v, o);
        if (threadIdx.x == 0) d_gap[bc] = v * (1.0f / (float)SPAT);
    }
}

// ---------------------------------------------------------------------------
// Kernel 2: reduce FC + fc1 + sigmoid. Single block.
// ---------------------------------------------------------------------------
__global__ void fc_kernel(const float* __restrict__ w_reduce,
                          const float* __restrict__ b_reduce,
                          const float* __restrict__ w_fc1,
                          const float* __restrict__ b_fc1) {
    __shared__ float sg[B_ * 16];
    const int tid = threadIdx.x;
    if (tid < B_ * 16) {
        int b = tid >> 4, j = tid & 15;
        float s = b_reduce[j];
        #pragma unroll 4
        for (int i = 0; i < 64; i++) s += d_gap[b * 64 + i] * w_reduce[j * 64 + i];
        sg[b * 16 + j] = s;
    }
    __syncthreads();
    for (int idx = tid; idx < B_ * 128; idx += 256) {
        int b = idx >> 7, c = idx & 127;
        float s = b_fc1[c];
        #pragma unroll
        for (int i = 0; i < 16; i++) s += sg[b * 16 + i] * w_fc1[c * 16 + i];
        d_h[idx] = 1.0f / (1.0f + expf(-s));
    }
}

// ---------------------------------------------------------------------------
// Kernel 3: dynamic weights -> mma a-fragment layout (hi and lo terms).
// ---------------------------------------------------------------------------
__global__ void wdyn_kernel(const float* __restrict__ w_fc2) {
    const int idx = blockIdx.x * blockDim.x + threadIdx.x;
    const int total = B_ * 4 * 27 * 2 * 4 * 32;   // 442368
    if (idx >= total) return;
    const int lane = idx & 31;
    const int mt   = (idx >> 5) & 3;
    const int term = (idx >> 7) & 1;
    int q = idx >> 8;
    const int tap = q % 27;  q /= 27;
    const int g   = q & 3;
    const int b   = q >> 2;

    unsigned r32[4];
    #pragma unroll
    for (int r = 0; r < 4; r++) {
        const int row = (lane >> 2) + (r & 1) * 8;
        const int kb  = 2 * (lane & 3) + (r >> 1) * 8;
        const int oc  = mt * 16 + row;
        unsigned e[2];
        #pragma unroll
        for (int j = 0; j < 2; j++) {
            const int ic = g * 16 + kb + j;
            const float v = w_fc2[oc * 1728 + ic * 27 + tap] *
                            d_h[b * 128 + oc * 2 + (ic >= 32 ? 1 : 0)];
            e[j] = term == 0 ? bf_hi(v) : bf_lo(v);
        }
        r32[r] = e[0] | (e[1] << 16);
    }
    d_wfrag[idx] = make_uint4(r32[0], r32[1], r32[2], r32[3]);
}

// ---------------------------------------------------------------------------
// Kernel 3b: x pre-pass (f32 -> bf16 hi/lo, smem-row layout, halo pre-zeroed).
// ---------------------------------------------------------------------------
__global__ void prepass_kernel(const float* __restrict__ x) {
    const int i = blockIdx.x * 256 + threadIdx.x;
    if (i >= PR_ROWS) return;
    int j = i % WP;  int q = i / WP;
    int h = q % H_;  q /= H_;
    int t = q % T_;  q /= T_;
    int g = q & 3;
    int b = q >> 2;

    uint4 h0 = make_uint4(0, 0, 0, 0), h1 = h0, l0 = h0, l1 = h0;
    const int gw = j - 1;
    if ((unsigned)gw < (unsigned)W_) {
        const float* p = x + ((size_t)(b * C_ + g * 16) * T_ + t) * TH_STRIDE +
                         h * W_ + gw;
        unsigned hh[8], ll[8];
        #pragma unroll
        for (int k = 0; k < 8; k++) {
            float v0 = __ldg(p + (size_t)(2 * k) * SPAT);
            float v1 = __ldg(p + (size_t)(2 * k + 1) * SPAT);
            hh[k] = bf_hi(v0) | (bf_hi(v1) << 16);
            ll[k] = bf_lo(v0) | (bf_lo(v1) << 16);
        }
        h0 = make_uint4(hh[0], hh[1], hh[2], hh[3]);
        h1 = make_uint4(hh[4], hh[5], hh[6], hh[7]);
        l0 = make_uint4(ll[0], ll[1], ll[2], ll[3]);
        l1 = make_uint4(ll[4], ll[5], ll[6], ll[7]);
    }
    d_xh[(size_t)i * 2]     = h0;
    d_xh[(size_t)i * 2 + 1] = h1;
    d_xl[(size_t)i * 2]     = l0;
    d_xl[(size_t)i * 2 + 1] = l1;
}

// ---------------------------------------------------------------------------
// Kernel 4: persistent implicit-GEMM conv (mma.sync bf16, 3-term hi/lo).
// 148 CTAs walk flattened (tile, g) stages, cp.async double-buffered across
// ALL stage boundaries (incl. tile->tile). Inner tap loop = Round-8 form
// (bl+bh per tap, W frags one tap ahead). No bh pipeline.
// ---------------------------------------------------------------------------
extern __shared__ char smem[];

__global__ void __launch_bounds__(256, 1)
conv_kernel(float* __restrict__ out) {
    const int p = blockIdx.x;
    if (p >= NTILES) return;
    const int ntiles_mine = (NTILES - p + GRIDP - 1) / GRIDP;

    const int tid = threadIdx.x;
    const int wid = tid >> 5;
    const int lane = tid & 31;
    const unsigned sb = smem_u32(smem);

    const int rb_off = (lane & 7) + ((lane >> 4) & 1) * 8;
    const int bhalf  = (lane >> 3) & 1;

    auto coords = [](int tt, int& b, int& t, int& h0) {
        b = tt / 240;
        int r = tt - b * 240;
        t = r >> 3;
        h0 = (r & 7) * 8;
    };

    // ---- stage prefetch: fill buffer `buf` for (b,t,h0,g) via zfill cp.async
    auto prefetch = [&](int b, int t, int h0, int g, int buf) {
        const char* xh8 = reinterpret_cast<const char*>(d_xh);
        const char* xl8 = reinterpret_cast<const char*>(d_xl);
        #pragma unroll 1
        for (int i = tid; i < 2 * ROWS * 2; i += 256) {
            const int term = i >= 2 * ROWS;
            const int rem  = term ? i - 2 * ROWS : i;
            const int r  = rem >> 1;
            const int hb = rem & 1;
            int t2 = r / (HP * WP);
            int rr = r - t2 * (HP * WP);
            int hp = rr / WP;
            int wp = rr - hp * WP;
            const int gt = t + t2 - 1, gh = h0 + hp - 1;
            const unsigned ok =
                (((unsigned)gt < (unsigned)T_) & ((unsigned)gh < (unsigned)H_))
                ? 16u : 0u;
            const int gtc = gt < 0 ? 0 : (gt >= T_ ? T_ - 1 : gt);
            const int ghc = gh < 0 ? 0 : (gh >= H_ ? H_ - 1 : gh);
            const size_t srow =
                ((((size_t)(b * 4 + g) * T_ + gtc) * H_ + ghc) * WP + wp);
            const char* src = (term ? xl8 : xh8) + srow * 32 + hb * 16;
            const unsigned dst = sb + buf * BUFB + term * SLABB + r * 32 +
                                 ((((r >> 2) & 1) ^ hb) << 4);
            cp16(dst, src, ok);
        }
        cp_commit();
    };

    float acc[4][6][4];
    #pragma unroll
    for (int mt = 0; mt < 4; mt++)
        #pragma unroll
        for (int nt = 0; nt < 6; nt++)
            #pragma unroll
            for (int k = 0; k < 4; k++) acc[mt][nt][k] = 0.f;

    int tt = p, b, t, h0;
    coords(tt, b, t, h0);
    prefetch(b, t, h0, 0, 0);

    // preload W frags for (b, g=0, tap=0)
    uint4 whc[4], wlc[4];
    {
        const uint4* wt = d_wfrag + (size_t)(b * 4) * 27 * 256 + lane;
        #pragma unroll
        for (int mt = 0; mt < 4; mt++) {
            whc[mt] = __ldg(wt + mt * 32);
            wlc[mt] = __ldg(wt + 128 + mt * 32);
        }
    }

    int buf = 0;
    #pragma unroll 1
    for (int ti = 0; ti < ntiles_mine; ti++) {
        const bool last_tile = (ti == ntiles_mine - 1);
        int nb = b, nt_ = t, nh0 = h0;
        if (!last_tile) coords(tt + GRIDP, nb, nt_, nh0);

        #pragma unroll 1
        for (int g = 0; g < 4; g++) {
            cp_wait0();
            __syncthreads();
            // issue next-stage fill (crosses tile boundary at g==3)
            if (g < 3)            prefetch(b, t, h0, g + 1, buf ^ 1);
            else if (!last_tile)  prefetch(nb, nt_, nh0, 0, buf ^ 1);

            const unsigned sl_h = sb + buf * BUFB;
            const unsigned sl_l = sl_h + SLABB;

            const uint4* wf_cur = d_wfrag + (size_t)((b * 4 + g) * 27) * 256 + lane;
            const uint4* wf_next =
                (g < 3) ? wf_cur + 27 * 256
                        : (!last_tile ? d_wfrag + (size_t)(nb * 4) * 27 * 256 + lane
                                      : wf_cur + 26 * 256);   // clamp at very end

            #pragma unroll 1
            for (int tap = 0; tap < 27; tap++) {
                // ---- W prefetch for next tap / next stage ----
                const uint4* wt = (tap < 26) ? wf_cur + (size_t)(tap + 1) * 256
                                             : wf_next;
                uint4 whn[4], wln[4];
                #pragma unroll
                for (int mt = 0; mt < 4; mt++) {
                    whn[mt] = __ldg(wt + mt * 32);
                    wln[mt] = __ldg(wt + 128 + mt * 32);
                }

                // ---- B fragments for current tap (R8 form) ----
                const int dt2 = tap / 9;
                const int rem = tap - dt2 * 9;
                const int dh  = rem / 3;
                const int dw  = rem - dh * 3;
                const int shift = (dt2 * HP + dh) * WP + dw;

                unsigned bh[12], bl[12];
                #pragma unroll
                for (int q = 0; q < 3; q++) {
                    int r = wid * 48 + q * 16 + rb_off + shift;
                    unsigned a = r * 32 + (((((r >> 2) & 1) ^ bhalf)) << 4);
                    ldmx4(bh[q * 4], bh[q * 4 + 1], bh[q * 4 + 2], bh[q * 4 + 3],
                          sl_h + a);
                    ldmx4(bl[q * 4], bl[q * 4 + 1], bl[q * 4 + 2], bl[q * 4 + 3],
                          sl_l + a);
                }

                // ---- mma with current (preloaded) W fragments ----
                #pragma unroll
                for (int mt = 0; mt < 4; mt++) {
                    #pragma unroll
                    for (int nt = 0; nt < 6; nt++) {
                        const int q = nt >> 1, pr = (nt & 1) * 2;
                        mma_bf16(acc[mt][nt], whc[mt],
                                 bh[q * 4 + pr], bh[q * 4 + pr + 1]);
                        mma_bf16(acc[mt][nt], whc[mt],
                                 bl[q * 4 + pr], bl[q * 4 + pr + 1]);
                        mma_bf16(acc[mt][nt], wlc[mt],
                                 bh[q * 4 + pr], bh[q * 4 + pr + 1]);
                    }
                }

                // ---- rotate W pipeline ----
                #pragma unroll
                for (int mt = 0; mt < 4; mt++) {
                    whc[mt] = whn[mt];
                    wlc[mt] = wln[mt];
                }
            }
            buf ^= 1;
        }

        // ---- epilogue for this tile (cross-tile fill already in flight) ----
        {
            const int gh = h0 + wid;
            #pragma unroll
            for (int mt = 0; mt < 4; mt++) {
                const int oc0 = mt * 16 + (lane >> 2);
                #pragma unroll
                for (int nt = 0; nt < 6; nt++) {
                    const int wc = nt * 8 + 2 * (lane & 3);
                    if (wc < W_) {
                        size_t o0 = ((size_t)(b * C_ + oc0) * T_ + t) * TH_STRIDE +
                                    gh * W_ + wc;
                        size_t o1 = o0 + (size_t)8 * SPAT;
                        *(float2*)(out + o0) =
                            make_float2(acc[mt][nt][0], acc[mt][nt][1]);
                        *(float2*)(out + o1) =
                            make_float2(acc[mt][nt][2], acc[mt][nt][3]);
                    }
                    #pragma unroll
                    for (int k = 0; k < 4; k++) acc[mt][nt][k] = 0.f;
                }
            }
        }

        tt += GRIDP; b = nb; t = nt_; h0 = nh0;
    }
}

// ---------------------------------------------------------------------------
extern "C" void kernel_launch(void* const* d_in, const int* in_sizes, int n_in,
                              void* d_out, int out_size) {
    const float* x        = (const float*)d_in[0];
    const float* w_reduce = (const float*)d_in[1];
    const float* b_reduce = (const float*)d_in[2];
    const float* w_fc1    = (const float*)d_in[3];
    const float* b_fc1    = (const float*)d_in[4];
    const float* w_fc2    = (const float*)d_in[5];
    float* out = (float*)d_out;

    cudaFuncSetAttribute(conv_kernel,
                         cudaFuncAttributeMaxDynamicSharedMemorySize, SM_TOTAL);

    gap_kernel<<<B_ * C_, 256>>>(x);
    fc_kernel<<<1, 256>>>(w_reduce, b_reduce, w_fc1, b_fc1);
    {
        const int total = B_ * 4 * 27 * 2 * 4 * 32;
        wdyn_kernel<<<(total + 255) / 256, 256>>>(w_fc2);
    }
    prepass_kernel<<<(PR_ROWS + 255) / 256, 256>>>(x);
    conv_kernel<<<GRIDP, 256, SM_TOTAL>>>(out);
}

// round 13
// speedup vs baseline: 1.1697x; 1.0847x over previous
#include <cuda_runtime.h>
#include <cuda_bf16.h>
#include <cstdint>
#include <cstddef>

// ---------------------------------------------------------------------------
// Problem constants
// ---------------------------------------------------------------------------
#define B_   16
#define C_   64
#define T_   30
#define H_   64
#define W_   44
#define SPAT (T_ * H_ * W_)        // 84480
#define TH_STRIDE (H_ * W_)        // 2816

// conv tiling (2 CTAs / SM)
#define HH 4                       // output h rows per block
#define HP 6                       // h rows incl halo
#define WP 48                      // padded w per row
#define ROWS (3 * HP * WP)         // 864 pixel rows per slab
#define ROWSP 880                  // padded rows (ldmatrix tap-shift bleed, max r=865)
#define SLABB (ROWSP * 32)         // 28160 B per term slab
#define BUFB  (2 * SLABB)          // 56320 B per buffer (xh + xl)
#define SM_TOTAL (2 * BUFB)        // 112640 B per CTA (double buffered)

#define NTHR 128                   // 4 warps

#define PR_ROWS (B_ * 4 * T_ * H_ * WP)   // 5,898,240 scratch rows

// Scratch (static device globals; no allocation)
__device__ float d_gap[B_ * C_];
__device__ float d_h[B_ * 128];
// W fragments, mma-lane order: [b][g:4][tap:27][term:2][mt:4][lane:32] uint4
__device__ uint4 d_wfrag[B_ * 4 * 27 * 2 * 4 * 32];
// x hi/lo bf16 scratch, smem-row layout: [b][g][t][h][j:48] rows of 32B (16 ic)
__device__ uint4 d_xh[PR_ROWS * 2];
__device__ uint4 d_xl[PR_ROWS * 2];

// ---------------------------------------------------------------------------
// helpers
// ---------------------------------------------------------------------------
__device__ __forceinline__ unsigned smem_u32(const void* p) {
    unsigned a;
    asm("{ .reg .u64 t; cvta.to.shared.u64 t, %1; cvt.u32.u64 %0, t; }"
        : "=r"(a) : "l"(p));
    return a;
}
__device__ __forceinline__ void ldmx4(unsigned& r0, unsigned& r1,
                                      unsigned& r2, unsigned& r3, unsigned a) {
    asm volatile("ldmatrix.sync.aligned.m8n8.x4.shared.b16 {%0,%1,%2,%3}, [%4];"
                 : "=r"(r0), "=r"(r1), "=r"(r2), "=r"(r3) : "r"(a));
}
__device__ __forceinline__ void mma_bf16(float* c, const uint4 a,
                                         unsigned b0, unsigned b1) {
    asm volatile(
        "mma.sync.aligned.m16n8k16.row.col.f32.bf16.bf16.f32 "
        "{%0,%1,%2,%3}, {%4,%5,%6,%7}, {%8,%9}, {%0,%1,%2,%3};"
        : "+f"(c[0]), "+f"(c[1]), "+f"(c[2]), "+f"(c[3])
        : "r"(a.x), "r"(a.y), "r"(a.z), "r"(a.w), "r"(b0), "r"(b1));
}
__device__ __forceinline__ unsigned bf_hi(float v) {
    return (unsigned)__bfloat16_as_ushort(__float2bfloat16_rn(v));
}
__device__ __forceinline__ unsigned bf_lo(float v) {
    float hf = __bfloat162float(__float2bfloat16_rn(v));
    return (unsigned)__bfloat16_as_ushort(__float2bfloat16_rn(v - hf));
}
__device__ __forceinline__ void cp16(unsigned dst, const void* src, unsigned sz) {
    asm volatile("cp.async.cg.shared.global [%0], [%1], 16, %2;"
                 :: "r"(dst), "l"(src), "r"(sz) : "memory");
}
__device__ __forceinline__ void cp_commit() {
    asm volatile("cp.async.commit_group;" ::: "memory");
}
__device__ __forceinline__ void cp_wait0() {
    asm volatile("cp.async.wait_group 0;" ::: "memory");
}

// ---------------------------------------------------------------------------
// Kernel 1: global average pool. 1024 blocks.
// ---------------------------------------------------------------------------
__global__ void gap_kernel(const float* __restrict__ x) {
    const int bc = blockIdx.x;
    const float4* xp = reinterpret_cast<const float4*>(x) + (size_t)bc * (SPAT / 4);
    float s = 0.f;
    for (int i = threadIdx.x; i < SPAT / 4; i += 256) {
        float4 v = xp[i];
        s += (v.x + v.y) + (v.z + v.w);
    }
    #pragma unroll
    for (int o = 16; o > 0; o >>= 1) s += __shfl_xor_sync(0xffffffffu, s, o);
    __shared__ float red[8];
    if ((threadIdx.x & 31) == 0) red[threadIdx.x >> 5] = s;
    __syncthreads();
    if (threadIdx.x < 8) {
        float v = red[threadIdx.x];
        #pragma unroll
        for (int o = 4; o > 0; o >>= 1) v += __shfl_xor_sync(0xffu, v, o);
        if (threadIdx.x == 0) d_gap[bc] = v * (1.0f / (float)SPAT);
    }
}

// ---------------------------------------------------------------------------
// Kernel 2: reduce FC + fc1 + sigmoid. Single block.
// ---------------------------------------------------------------------------
__global__ void fc_kernel(const float* __restrict__ w_reduce,
                          const float* __restrict__ b_reduce,
                          const float* __restrict__ w_fc1,
                          const float* __restrict__ b_fc1) {
    __shared__ float sg[B_ * 16];
    const int tid = threadIdx.x;
    if (tid < B_ * 16) {
        int b = tid >> 4, j = tid & 15;
        float s = b_reduce[j];
        #pragma unroll 4
        for (int i = 0; i < 64; i++) s += d_gap[b * 64 + i] * w_reduce[j * 64 + i];
        sg[b * 16 + j] = s;
    }
    __syncthreads();
    for (int idx = tid; idx < B_ * 128; idx += 256) {
        int b = idx >> 7, c = idx & 127;
        float s = b_fc1[c];
        #pragma unroll
        for (int i = 0; i < 16; i++) s += sg[b * 16 + i] * w_fc1[c * 16 + i];
        d_h[idx] = 1.0f / (1.0f + expf(-s));
    }
}

// ---------------------------------------------------------------------------
// Kernel 3: dynamic weights -> mma a-fragment layout (hi and lo terms).
// ---------------------------------------------------------------------------
__global__ void wdyn_kernel(const float* __restrict__ w_fc2) {
    const int idx = blockIdx.x * blockDim.x + threadIdx.x;
    const int total = B_ * 4 * 27 * 2 * 4 * 32;   // 442368
    if (idx >= total) return;
    const int lane = idx & 31;
    const int mt   = (idx >> 5) & 3;
    const int term = (idx >> 7) & 1;
    int q = idx >> 8;
    const int tap = q % 27;  q /= 27;
    const int g   = q & 3;
    const int b   = q >> 2;

    unsigned r32[4];
    #pragma unroll
    for (int r = 0; r < 4; r++) {
        const int row = (lane >> 2) + (r & 1) * 8;
        const int kb  = 2 * (lane & 3) + (r >> 1) * 8;
        const int oc  = mt * 16 + row;
        unsigned e[2];
        #pragma unroll
        for (int j = 0; j < 2; j++) {
            const int ic = g * 16 + kb + j;
            const float v = w_fc2[oc * 1728 + ic * 27 + tap] *
                            d_h[b * 128 + oc * 2 + (ic >= 32 ? 1 : 0)];
            e[j] = term == 0 ? bf_hi(v) : bf_lo(v);
        }
        r32[r] = e[0] | (e[1] << 16);
    }
    d_wfrag[idx] = make_uint4(r32[0], r32[1], r32[2], r32[3]);
}

// ---------------------------------------------------------------------------
// Kernel 3b: x pre-pass (f32 -> bf16 hi/lo, smem-row layout, halo pre-zeroed).
// ---------------------------------------------------------------------------
__global__ void prepass_kernel(const float* __restrict__ x) {
    const int i = blockIdx.x * 256 + threadIdx.x;
    if (i >= PR_ROWS) return;
    int j = i % WP;  int q = i / WP;
    int h = q % H_;  q /= H_;
    int t = q % T_;  q /= T_;
    int g = q & 3;
    int b = q >> 2;

    uint4 h0 = make_uint4(0, 0, 0, 0), h1 = h0, l0 = h0, l1 = h0;
    const int gw = j - 1;
    if ((unsigned)gw < (unsigned)W_) {
        const float* p = x + ((size_t)(b * C_ + g * 16) * T_ + t) * TH_STRIDE +
                         h * W_ + gw;
        unsigned hh[8], ll[8];
        #pragma unroll
        for (int k = 0; k < 8; k++) {
            float v0 = __ldg(p + (size_t)(2 * k) * SPAT);
            float v1 = __ldg(p + (size_t)(2 * k + 1) * SPAT);
            hh[k] = bf_hi(v0) | (bf_hi(v1) << 16);
            ll[k] = bf_lo(v0) | (bf_lo(v1) << 16);
        }
        h0 = make_uint4(hh[0], hh[1], hh[2], hh[3]);
        h1 = make_uint4(hh[4], hh[5], hh[6], hh[7]);
        l0 = make_uint4(ll[0], ll[1], ll[2], ll[3]);
        l1 = make_uint4(ll[4], ll[5], ll[6], ll[7]);
    }
    d_xh[(size_t)i * 2]     = h0;
    d_xh[(size_t)i * 2 + 1] = h1;
    d_xl[(size_t)i * 2]     = l0;
    d_xl[(size_t)i * 2 + 1] = l1;
}

// ---------------------------------------------------------------------------
// Kernel 4: implicit-GEMM conv via mma.sync bf16 (3-term hi/lo split).
// R8 structure at half tile: 4 warps, warp = m64(oc) x n48(one h row),
// cp.async double-buffered A slabs, W frags one tap ahead.
// 2 CTAs co-resident per SM (smem 110KB/CTA, 128 thr) overlap phases.
// ---------------------------------------------------------------------------
extern __shared__ char smem[];

__global__ void __launch_bounds__(NTHR, 2)
conv_kernel(float* __restrict__ out) {
    const int t  = blockIdx.x;
    const int h0 = blockIdx.y * HH;
    const int b  = blockIdx.z;
    const int tid = threadIdx.x;
    const int wid = tid >> 5;
    const int lane = tid & 31;

    const unsigned sb = smem_u32(smem);

    float acc[4][6][4];
    #pragma unroll
    for (int mt = 0; mt < 4; mt++)
        #pragma unroll
        for (int nt = 0; nt < 6; nt++)
            #pragma unroll
            for (int k = 0; k < 4; k++) acc[mt][nt][k] = 0.f;

    // ldmatrix lane address components
    const int rb_off = (lane & 7) + ((lane >> 4) & 1) * 8;
    const int bhalf  = (lane >> 3) & 1;

    // ---- prefetch: fill buffer `buf` with group `g` slabs (zfill halo) ----
    auto prefetch = [&](int g, int buf) {
        const char* xh8 = reinterpret_cast<const char*>(d_xh);
        const char* xl8 = reinterpret_cast<const char*>(d_xl);
        #pragma unroll 1
        for (int i = tid; i < 2 * ROWS * 2; i += NTHR) {   // 3456 16B ops
            const int term = i >= 2 * ROWS;
            const int rem  = term ? i - 2 * ROWS : i;
            const int r  = rem >> 1;
            const int hb = rem & 1;
            int t2 = r / (HP * WP);
            int rr = r - t2 * (HP * WP);
            int hp = rr / WP;
            int wp = rr - hp * WP;
            const int gt = t + t2 - 1, gh = h0 + hp - 1;
            const unsigned ok =
                (((unsigned)gt < (unsigned)T_) & ((unsigned)gh < (unsigned)H_))
                ? 16u : 0u;
            const int gtc = gt < 0 ? 0 : (gt >= T_ ? T_ - 1 : gt);
            const int ghc = gh < 0 ? 0 : (gh >= H_ ? H_ - 1 : gh);
            const size_t srow =
                ((((size_t)(b * 4 + g) * T_ + gtc) * H_ + ghc) * WP + wp);
            const char* src = (term ? xl8 : xh8) + srow * 32 + hb * 16;
            const unsigned dst = sb + buf * BUFB + term * SLABB + r * 32 +
                                 ((((r >> 2) & 1) ^ hb) << 4);
            cp16(dst, src, ok);
        }
        cp_commit();
    };

    prefetch(0, 0);

    // W-fragment pointer for flat k = g*27 + tap (clamped at the end)
    const uint4* wf0 = d_wfrag + (size_t)(b * 4) * 27 * 256 + lane;
    auto wptr = [&](int k) { return wf0 + (size_t)k * 256; };

    // preload W fragments for k = 0
    uint4 whc[4], wlc[4];
    {
        const uint4* wt = wptr(0);
        #pragma unroll
        for (int mt = 0; mt < 4; mt++) {
            whc[mt] = __ldg(wt + mt * 32);
            wlc[mt] = __ldg(wt + 128 + mt * 32);
        }
    }

    #pragma unroll 1
    for (int g = 0; g < 4; g++) {
        cp_wait0();
        __syncthreads();
        if (g < 3) prefetch(g + 1, (g + 1) & 1);

        const unsigned sl_h = sb + (g & 1) * BUFB;
        const unsigned sl_l = sl_h + SLABB;

        #pragma unroll 1
        for (int tap = 0; tap < 27; tap++) {
            // ---- prefetch next tap's W fragments (one tap / g ahead) ----
            const int kf = g * 27 + tap;
            const uint4* wt = wptr(kf < 107 ? kf + 1 : 107);
            uint4 whn[4], wln[4];
            #pragma unroll
            for (int mt = 0; mt < 4; mt++) {
                whn[mt] = __ldg(wt + mt * 32);
                wln[mt] = __ldg(wt + 128 + mt * 32);
            }

            // ---- B fragments for current tap ----
            const int dt2 = tap / 9;
            const int rem = tap - dt2 * 9;
            const int dh  = rem / 3;
            const int dw  = rem - dh * 3;
            const int shift = (dt2 * HP + dh) * WP + dw;

            unsigned bh[12], bl[12];
            #pragma unroll
            for (int q = 0; q < 3; q++) {
                int r = wid * 48 + q * 16 + rb_off + shift;
                unsigned a = r * 32 + (((((r >> 2) & 1) ^ bhalf)) << 4);
                ldmx4(bh[q * 4], bh[q * 4 + 1], bh[q * 4 + 2], bh[q * 4 + 3],
                      sl_h + a);
                ldmx4(bl[q * 4], bl[q * 4 + 1], bl[q * 4 + 2], bl[q * 4 + 3],
                      sl_l + a);
            }

            // ---- mma with current (preloaded) W fragments ----
            #pragma unroll
            for (int mt = 0; mt < 4; mt++) {
                #pragma unroll
                for (int nt = 0; nt < 6; nt++) {
                    const int q = nt >> 1, pr = (nt & 1) * 2;
                    mma_bf16(acc[mt][nt], whc[mt], bh[q * 4 + pr], bh[q * 4 + pr + 1]);
                    mma_bf16(acc[mt][nt], whc[mt], bl[q * 4 + pr], bl[q * 4 + pr + 1]);
                    mma_bf16(acc[mt][nt], wlc[mt], bh[q * 4 + pr], bh[q * 4 + pr + 1]);
                }
            }

            // ---- rotate pipeline ----
            #pragma unroll
            for (int mt = 0; mt < 4; mt++) {
                whc[mt] = whn[mt];
                wlc[mt] = wln[mt];
            }
        }
    }

    // ---- epilogue ----
    const int gh = h0 + wid;
    #pragma unroll
    for (int mt = 0; mt < 4; mt++) {
        const int oc0 = mt * 16 + (lane >> 2);
        #pragma unroll
        for (int nt = 0; nt < 6; nt++) {
            const int wc = nt * 8 + 2 * (lane & 3);
            if (wc < W_) {
                size_t o0 = ((size_t)(b * C_ + oc0) * T_ + t) * TH_STRIDE +
                            gh * W_ + wc;
                size_t o1 = o0 + (size_t)8 * SPAT;
                *(float2*)(out + o0) = make_float2(acc[mt][nt][0], acc[mt][nt][1]);
                *(float2*)(out + o1) = make_float2(acc[mt][nt][2], acc[mt][nt][3]);
            }
        }
    }
}

// ---------------------------------------------------------------------------
extern "C" void kernel_launch(void* const* d_in, const int* in_sizes, int n_in,
                              void* d_out, int out_size) {
    const float* x        = (const float*)d_in[0];
    const float* w_reduce = (const float*)d_in[1];
    const float* b_reduce = (const float*)d_in[2];
    const float* w_fc1    = (const float*)d_in[3];
    const float* b_fc1    = (const float*)d_in[4];
    const float* w_fc2    = (const float*)d_in[5];
    float* out = (float*)d_out;

    cudaFuncSetAttribute(conv_kernel,
                         cudaFuncAttributeMaxDynamicSharedMemorySize, SM_TOTAL);

    gap_kernel<<<B_ * C_, 256>>>(x);
    fc_kernel<<<1, 256>>>(w_reduce, b_reduce, w_fc1, b_fc1);
    {
        const int total = B_ * 4 * 27 * 2 * 4 * 32;
        wdyn_kernel<<<(total + 255) / 256, 256>>>(w_fc2);
    }
    prepass_kernel<<<(PR_ROWS + 255) / 256, 256>>>(x);
    {
        dim3 grid(T_, H_ / HH, B_);   // (30, 16, 16) = 7680 blocks
        conv_kernel<<<grid, NTHR, SM_TOTAL>>>(out);
    }
}

// round 14
// speedup vs baseline: 1.1710x; 1.0011x over previous
#include <cuda_runtime.h>
#include <cuda_bf16.h>
#include <cstdint>
#include <cstddef>

// ---------------------------------------------------------------------------
// Problem constants
// ---------------------------------------------------------------------------
#define B_   16
#define C_   64
#define T_   30
#define H_   64
#define W_   44
#define SPAT (T_ * H_ * W_)        // 84480
#define TH_STRIDE (H_ * W_)        // 2816

// conv tiling (2 CTAs / SM)
#define HH 4                       // output h rows per block
#define HP 6                       // h rows incl halo
#define WP 48                      // padded w per row
#define ROWS (3 * HP * WP)         // 864 pixel rows per slab
#define ROWSP 880                  // padded rows (ldmatrix tap-shift bleed, max r=865)
#define SLABB (ROWSP * 32)         // 28160 B per term slab
#define BUFB  (2 * SLABB)          // 56320 B per buffer (xh + xl)
#define SM_TOTAL (2 * BUFB)        // 112640 B per CTA (double buffered)

#define NTHR 128                   // 4 warps

#define PR_ROWS (B_ * 4 * T_ * H_ * WP)   // 5,898,240 scratch rows

// Scratch (static device globals; no allocation)
__device__ float d_gap[B_ * C_];
__device__ float d_h[B_ * 128];
// W fragments, mma-lane order: [b][g:4][tap:27][term:2][mt:4][lane:32] uint4
__device__ uint4 d_wfrag[B_ * 4 * 27 * 2 * 4 * 32];
// x hi/lo bf16 scratch, smem-row layout: [b][g][t][h][j:48] rows of 32B (16 ic)
__device__ uint4 d_xh[PR_ROWS * 2];
__device__ uint4 d_xl[PR_ROWS * 2];

// ---------------------------------------------------------------------------
// helpers
// ---------------------------------------------------------------------------
__device__ __forceinline__ unsigned smem_u32(const void* p) {
    unsigned a;
    asm("{ .reg .u64 t; cvta.to.shared.u64 t, %1; cvt.u32.u64 %0, t; }"
        : "=r"(a) : "l"(p));
    return a;
}
__device__ __forceinline__ void ldmx4(unsigned& r0, unsigned& r1,
                                      unsigned& r2, unsigned& r3, unsigned a) {
    asm volatile("ldmatrix.sync.aligned.m8n8.x4.shared.b16 {%0,%1,%2,%3}, [%4];"
                 : "=r"(r0), "=r"(r1), "=r"(r2), "=r"(r3) : "r"(a));
}
__device__ __forceinline__ void mma_bf16(float* c, const uint4 a,
                                         unsigned b0, unsigned b1) {
    asm volatile(
        "mma.sync.aligned.m16n8k16.row.col.f32.bf16.bf16.f32 "
        "{%0,%1,%2,%3}, {%4,%5,%6,%7}, {%8,%9}, {%0,%1,%2,%3};"
        : "+f"(c[0]), "+f"(c[1]), "+f"(c[2]), "+f"(c[3])
        : "r"(a.x), "r"(a.y), "r"(a.z), "r"(a.w), "r"(b0), "r"(b1));
}
__device__ __forceinline__ unsigned bf_hi(float v) {
    return (unsigned)__bfloat16_as_ushort(__float2bfloat16_rn(v));
}
__device__ __forceinline__ unsigned bf_lo(float v) {
    float hf = __bfloat162float(__float2bfloat16_rn(v));
    return (unsigned)__bfloat16_as_ushort(__float2bfloat16_rn(v - hf));
}
__device__ __forceinline__ void cp16(unsigned dst, const void* src, unsigned sz) {
    asm volatile("cp.async.cg.shared.global [%0], [%1], 16, %2;"
                 :: "r"(dst), "l"(src), "r"(sz) : "memory");
}
__device__ __forceinline__ void cp_commit() {
    asm volatile("cp.async.commit_group;" ::: "memory");
}
__device__ __forceinline__ void cp_wait0() {
    asm volatile("cp.async.wait_group 0;" ::: "memory");
}

// ---------------------------------------------------------------------------
// Kernel 1: global average pool. 1024 blocks.
// ---------------------------------------------------------------------------
__global__ void gap_kernel(const float* __restrict__ x) {
    const int bc = blockIdx.x;
    const float4* xp = reinterpret_cast<const float4*>(x) + (size_t)bc * (SPAT / 4);
    float s = 0.f;
    for (int i = threadIdx.x; i < SPAT / 4; i += 256) {
        float4 v = xp[i];
        s += (v.x + v.y) + (v.z + v.w);
    }
    #pragma unroll
    for (int o = 16; o > 0; o >>= 1) s += __shfl_xor_sync(0xffffffffu, s, o);
    __shared__ float red[8];
    if ((threadIdx.x & 31) == 0) red[threadIdx.x >> 5] = s;
    __syncthreads();
    if (threadIdx.x < 8) {
        float v = red[threadIdx.x];
        #pragma unroll
        for (int o = 4; o > 0; o >>= 1) v += __shfl_xor_sync(0xffu, v, o);
        if (threadIdx.x == 0) d_gap[bc] = v * (1.0f / (float)SPAT);
    }
}

// ---------------------------------------------------------------------------
// Kernel 2: reduce FC + fc1 + sigmoid. Single block.
// ---------------------------------------------------------------------------
__global__ void fc_kernel(const float* __restrict__ w_reduce,
                          const float* __restrict__ b_reduce,
                          const float* __restrict__ w_fc1,
                          const float* __restrict__ b_fc1) {
    __shared__ float sg[B_ * 16];
    const int tid = threadIdx.x;
    if (tid < B_ * 16) {
        int b = tid >> 4, j = tid & 15;
        float s = b_reduce[j];
        #pragma unroll 4
        for (int i = 0; i < 64; i++) s += d_gap[b * 64 + i] * w_reduce[j * 64 + i];
        sg[b * 16 + j] = s;
    }
    __syncthreads();
    for (int idx = tid; idx < B_ * 128; idx += 256) {
        int b = idx >> 7, c = idx & 127;
        float s = b_fc1[c];
        #pragma unroll
        for (int i = 0; i < 16; i++) s += sg[b * 16 + i] * w_fc1[c * 16 + i];
        d_h[idx] = 1.0f / (1.0f + expf(-s));
    }
}

// ---------------------------------------------------------------------------
// Kernel 3: dynamic weights -> mma a-fragment layout (hi and lo terms).
// ---------------------------------------------------------------------------
__global__ void wdyn_kernel(const float* __restrict__ w_fc2) {
    const int idx = blockIdx.x * blockDim.x + threadIdx.x;
    const int total = B_ * 4 * 27 * 2 * 4 * 32;   // 442368
    if (idx >= total) return;
    const int lane = idx & 31;
    const int mt   = (idx >> 5) & 3;
    const int term = (idx >> 7) & 1;
    int q = idx >> 8;
    const int tap = q % 27;  q /= 27;
    const int g   = q & 3;
    const int b   = q >> 2;

    unsigned r32[4];
    #pragma unroll
    for (int r = 0; r < 4; r++) {
        const int row = (lane >> 2) + (r & 1) * 8;
        const int kb  = 2 * (lane & 3) + (r >> 1) * 8;
        const int oc  = mt * 16 + row;
        unsigned e[2];
        #pragma unroll
        for (int j = 0; j < 2; j++) {
            const int ic = g * 16 + kb + j;
            const float v = w_fc2[oc * 1728 + ic * 27 + tap] *
                            d_h[b * 128 + oc * 2 + (ic >= 32 ? 1 : 0)];
            e[j] = term == 0 ? bf_hi(v) : bf_lo(v);
        }
        r32[r] = e[0] | (e[1] << 16);
    }
    d_wfrag[idx] = make_uint4(r32[0], r32[1], r32[2], r32[3]);
}

// ---------------------------------------------------------------------------
// Kernel 3b: x pre-pass (f32 -> bf16 hi/lo, smem-row layout, halo pre-zeroed).
// ---------------------------------------------------------------------------
__global__ void prepass_kernel(const float* __restrict__ x) {
    const int i = blockIdx.x * 256 + threadIdx.x;
    if (i >= PR_ROWS) return;
    int j = i % WP;  int q = i / WP;
    int h = q % H_;  q /= H_;
    int t = q % T_;  q /= T_;
    int g = q & 3;
    int b = q >> 2;

    uint4 h0 = make_uint4(0, 0, 0, 0), h1 = h0, l0 = h0, l1 = h0;
    const int gw = j - 1;
    if ((unsigned)gw < (unsigned)W_) {
        const float* p = x + ((size_t)(b * C_ + g * 16) * T_ + t) * TH_STRIDE +
                         h * W_ + gw;
        unsigned hh[8], ll[8];
        #pragma unroll
        for (int k = 0; k < 8; k++) {
            float v0 = __ldg(p + (size_t)(2 * k) * SPAT);
            float v1 = __ldg(p + (size_t)(2 * k + 1) * SPAT);
            hh[k] = bf_hi(v0) | (bf_hi(v1) << 16);
            ll[k] = bf_lo(v0) | (bf_lo(v1) << 16);
        }
        h0 = make_uint4(hh[0], hh[1], hh[2], hh[3]);
        h1 = make_uint4(hh[4], hh[5], hh[6], hh[7]);
        l0 = make_uint4(ll[0], ll[1], ll[2], ll[3]);
        l1 = make_uint4(ll[4], ll[5], ll[6], ll[7]);
    }
    d_xh[(size_t)i * 2]     = h0;
    d_xh[(size_t)i * 2 + 1] = h1;
    d_xl[(size_t)i * 2]     = l0;
    d_xl[(size_t)i * 2 + 1] = l1;
}

// ---------------------------------------------------------------------------
// Kernel 4: implicit-GEMM conv via mma.sync bf16 (3-term hi/lo split).
// R13 structure (2 CTAs/SM, half tile, cp.async double buffer, W frags one
// tap ahead) with mma issue reordered TERM-OUTER: 3 groups of 24 independent
// mmas -> accumulator RAW reuse distance 24 (was 1).
// ---------------------------------------------------------------------------
extern __shared__ char smem[];

__global__ void __launch_bounds__(NTHR, 2)
conv_kernel(float* __restrict__ out) {
    const int t  = blockIdx.x;
    const int h0 = blockIdx.y * HH;
    const int b  = blockIdx.z;
    const int tid = threadIdx.x;
    const int wid = tid >> 5;
    const int lane = tid & 31;

    const unsigned sb = smem_u32(smem);

    float acc[4][6][4];
    #pragma unroll
    for (int mt = 0; mt < 4; mt++)
        #pragma unroll
        for (int nt = 0; nt < 6; nt++)
            #pragma unroll
            for (int k = 0; k < 4; k++) acc[mt][nt][k] = 0.f;

    // ldmatrix lane address components
    const int rb_off = (lane & 7) + ((lane >> 4) & 1) * 8;
    const int bhalf  = (lane >> 3) & 1;

    // ---- prefetch: fill buffer `buf` with group `g` slabs (zfill halo) ----
    auto prefetch = [&](int g, int buf) {
        const char* xh8 = reinterpret_cast<const char*>(d_xh);
        const char* xl8 = reinterpret_cast<const char*>(d_xl);
        #pragma unroll 1
        for (int i = tid; i < 2 * ROWS * 2; i += NTHR) {   // 3456 16B ops
            const int term = i >= 2 * ROWS;
            const int rem  = term ? i - 2 * ROWS : i;
            const int r  = rem >> 1;
            const int hb = rem & 1;
            int t2 = r / (HP * WP);
            int rr = r - t2 * (HP * WP);
            int hp = rr / WP;
            int wp = rr - hp * WP;
            const int gt = t + t2 - 1, gh = h0 + hp - 1;
            const unsigned ok =
                (((unsigned)gt < (unsigned)T_) & ((unsigned)gh < (unsigned)H_))
                ? 16u : 0u;
            const int gtc = gt < 0 ? 0 : (gt >= T_ ? T_ - 1 : gt);
            const int ghc = gh < 0 ? 0 : (gh >= H_ ? H_ - 1 : gh);
            const size_t srow =
                ((((size_t)(b * 4 + g) * T_ + gtc) * H_ + ghc) * WP + wp);
            const char* src = (term ? xl8 : xh8) + srow * 32 + hb * 16;
            const unsigned dst = sb + buf * BUFB + term * SLABB + r * 32 +
                                 ((((r >> 2) & 1) ^ hb) << 4);
            cp16(dst, src, ok);
        }
        cp_commit();
    };

    prefetch(0, 0);

    // W-fragment pointer for flat k = g*27 + tap (clamped at the end)
    const uint4* wf0 = d_wfrag + (size_t)(b * 4) * 27 * 256 + lane;
    auto wptr = [&](int k) { return wf0 + (size_t)k * 256; };

    // preload W fragments for k = 0
    uint4 whc[4], wlc[4];
    {
        const uint4* wt = wptr(0);
        #pragma unroll
        for (int mt = 0; mt < 4; mt++) {
            whc[mt] = __ldg(wt + mt * 32);
            wlc[mt] = __ldg(wt + 128 + mt * 32);
        }
    }

    #pragma unroll 1
    for (int g = 0; g < 4; g++) {
        cp_wait0();
        __syncthreads();
        if (g < 3) prefetch(g + 1, (g + 1) & 1);

        const unsigned sl_h = sb + (g & 1) * BUFB;
        const unsigned sl_l = sl_h + SLABB;

        #pragma unroll 1
        for (int tap = 0; tap < 27; tap++) {
            // ---- prefetch next tap's W fragments (one tap / g ahead) ----
            const int kf = g * 27 + tap;
            const uint4* wt = wptr(kf < 107 ? kf + 1 : 107);
            uint4 whn[4], wln[4];
            #pragma unroll
            for (int mt = 0; mt < 4; mt++) {
                whn[mt] = __ldg(wt + mt * 32);
                wln[mt] = __ldg(wt + 128 + mt * 32);
            }

            // ---- B fragments for current tap ----
            const int dt2 = tap / 9;
            const int rem = tap - dt2 * 9;
            const int dh  = rem / 3;
            const int dw  = rem - dh * 3;
            const int shift = (dt2 * HP + dh) * WP + dw;

            unsigned bh[12], bl[12];
            #pragma unroll
            for (int q = 0; q < 3; q++) {
                int r = wid * 48 + q * 16 + rb_off + shift;
                unsigned a = r * 32 + (((((r >> 2) & 1) ^ bhalf)) << 4);
                ldmx4(bh[q * 4], bh[q * 4 + 1], bh[q * 4 + 2], bh[q * 4 + 3],
                      sl_h + a);
                ldmx4(bl[q * 4], bl[q * 4 + 1], bl[q * 4 + 2], bl[q * 4 + 3],
                      sl_l + a);
            }

            // ---- mma, TERM-OUTER: 24 independent mmas per group ----
            // group A: wh * bh
            #pragma unroll
            for (int mt = 0; mt < 4; mt++)
                #pragma unroll
                for (int nt = 0; nt < 6; nt++) {
                    const int q = nt >> 1, pr = (nt & 1) * 2;
                    mma_bf16(acc[mt][nt], whc[mt],
                             bh[q * 4 + pr], bh[q * 4 + pr + 1]);
                }
            // group B: wh * bl
            #pragma unroll
            for (int mt = 0; mt < 4; mt++)
                #pragma unroll
                for (int nt = 0; nt < 6; nt++) {
                    const int q = nt >> 1, pr = (nt & 1) * 2;
                    mma_bf16(acc[mt][nt], whc[mt],
                             bl[q * 4 + pr], bl[q * 4 + pr + 1]);
                }
            // group C: wl * bh
            #pragma unroll
            for (int mt = 0; mt < 4; mt++)
                #pragma unroll
                for (int nt = 0; nt < 6; nt++) {
                    const int q = nt >> 1, pr = (nt & 1) * 2;
                    mma_bf16(acc[mt][nt], wlc[mt],
                             bh[q * 4 + pr], bh[q * 4 + pr + 1]);
                }

            // ---- rotate pipeline ----
            #pragma unroll
            for (int mt = 0; mt < 4; mt++) {
                whc[mt] = whn[mt];
                wlc[mt] = wln[mt];
            }
        }
    }

    // ---- epilogue ----
    const int gh = h0 + wid;
    #pragma unroll
    for (int mt = 0; mt < 4; mt++) {
        const int oc0 = mt * 16 + (lane >> 2);
        #pragma unroll
        for (int nt = 0; nt < 6; nt++) {
            const int wc = nt * 8 + 2 * (lane & 3);
            if (wc < W_) {
                size_t o0 = ((size_t)(b * C_ + oc0) * T_ + t) * TH_STRIDE +
                            gh * W_ + wc;
                size_t o1 = o0 + (size_t)8 * SPAT;
                *(float2*)(out + o0) = make_float2(acc[mt][nt][0], acc[mt][nt][1]);
                *(float2*)(out + o1) = make_float2(acc[mt][nt][2], acc[mt][nt][3]);
            }
        }
    }
}

// ---------------------------------------------------------------------------
extern "C" void kernel_launch(void* const* d_in, const int* in_sizes, int n_in,
                              void* d_out, int out_size) {
    const float* x        = (const float*)d_in[0];
    const float* w_reduce = (const float*)d_in[1];
    const float* b_reduce = (const float*)d_in[2];
    const float* w_fc1    = (const float*)d_in[3];
    const float* b_fc1    = (const float*)d_in[4];
    const float* w_fc2    = (const float*)d_in[5];
    float* out = (float*)d_out;

    cudaFuncSetAttribute(conv_kernel,
                         cudaFuncAttributeMaxDynamicSharedMemorySize, SM_TOTAL);

    gap_kernel<<<B_ * C_, 256>>>(x);
    fc_kernel<<<1, 256>>>(w_reduce, b_reduce, w_fc1, b_fc1);
    {
        const int total = B_ * 4 * 27 * 2 * 4 * 32;
        wdyn_kernel<<<(total + 255) / 256, 256>>>(w_fc2);
    }
    prepass_kernel<<<(PR_ROWS + 255) / 256, 256>>>(x);
    {
        dim3 grid(T_, H_ / HH, B_);   // (30, 16, 16) = 7680 blocks
        conv_kernel<<<grid, NTHR, SM_TOTAL>>>(out);
    }
}

// round 15
// speedup vs baseline: 1.6155x; 1.3796x over previous
#include <cuda_runtime.h>
#include <cstdint>
#include <cstddef>

// ---------------------------------------------------------------------------
// Problem constants
// ---------------------------------------------------------------------------
#define B_   16
#define C_   64
#define T_   30
#define H_   64
#define W_   44
#define SPAT (T_ * H_ * W_)        // 84480
#define TH_STRIDE (H_ * W_)        // 2816

// conv tiling
#define HH 4                       // output h rows per block
#define HP 6                       // h rows incl halo
#define WP 48                      // padded w per row
#define ROWS (3 * HP * WP)         // 864 pixel rows per slab
#define ROWSP 880                  // padded rows (ldmatrix tap-shift bleed, max r=865)
#define SLABB (ROWSP * 32)         // 28160 B per term slab (32 int8 ic per row)
#define BUFB  (2 * SLABB)          // 56320 B per buffer (Xh + Xl)
#define SM_TOTAL (2 * BUFB)        // 112640 B (double buffered)

#define NTHR 256                   // 8 warps: (h-row 0..3) x (m-half 0..1)

#define PR2_ROWS (B_ * 2 * T_ * H_ * WP)   // 2,949,120 scratch rows (2 ic-groups of 32)

// quant scales: x = 2^-4 (Xh + Xl/128), w = 2^-10 (Wh + Wl/128)
// out = 2^-14 * (acc_HH + acc_HLLH/128 + acc_LL/16384)

// Scratch (static device globals; no allocation)
__device__ float d_gap[B_ * C_];
__device__ float d_h[B_ * 128];
// W fragments, s8 k32 a-frag lane order: [b][g:2][tap:27][term:2][mt:4][lane:32] uint4
__device__ uint4 d_wfrag[B_ * 2 * 27 * 2 * 4 * 32];
// x int8 hi/lo scratch, smem-row layout: [b][g:2][t][h][j:48] rows of 32B (32 ic)
__device__ uint4 d_xh[PR2_ROWS * 2];
__device__ uint4 d_xl[PR2_ROWS * 2];

// ---------------------------------------------------------------------------
// helpers
// ---------------------------------------------------------------------------
__device__ __forceinline__ unsigned smem_u32(const void* p) {
    unsigned a;
    asm("{ .reg .u64 t; cvta.to.shared.u64 t, %1; cvt.u32.u64 %0, t; }"
        : "=r"(a) : "l"(p));
    return a;
}
__device__ __forceinline__ void ldmx4(unsigned& r0, unsigned& r1,
                                      unsigned& r2, unsigned& r3, unsigned a) {
    asm volatile("ldmatrix.sync.aligned.m8n8.x4.shared.b16 {%0,%1,%2,%3}, [%4];"
                 : "=r"(r0), "=r"(r1), "=r"(r2), "=r"(r3) : "r"(a));
}
__device__ __forceinline__ void mma_s8(int* c, const uint4 a,
                                       unsigned b0, unsigned b1) {
    asm volatile(
        "mma.sync.aligned.m16n8k32.row.col.s32.s8.s8.s32 "
        "{%0,%1,%2,%3}, {%4,%5,%6,%7}, {%8,%9}, {%0,%1,%2,%3};"
        : "+r"(c[0]), "+r"(c[1]), "+r"(c[2]), "+r"(c[3])
        : "r"(a.x), "r"(a.y), "r"(a.z), "r"(a.w), "r"(b0), "r"(b1));
}
__device__ __forceinline__ int q8clamp(float v) {
    int i = __float2int_rn(v);
    return i < -127 ? -127 : (i > 127 ? 127 : i);
}
// quantize v*16 -> (hi, lo): v ~ (hi + lo/128) / 16
__device__ __forceinline__ void quant_x(float v, int& h, int& l) {
    float s = v * 16.0f;
    h = q8clamp(s);
    l = q8clamp((s - (float)h) * 128.0f);
}
// quantize w*1024 -> (hi, lo): w ~ (hi + lo/128) / 1024
__device__ __forceinline__ void quant_w(float v, int& h, int& l) {
    float s = v * 1024.0f;
    h = q8clamp(s);
    l = q8clamp((s - (float)h) * 128.0f);
}
__device__ __forceinline__ unsigned pack4(int a, int b, int c, int d) {
    return (unsigned)(a & 0xff) | ((unsigned)(b & 0xff) << 8) |
           ((unsigned)(c & 0xff) << 16) | ((unsigned)(d & 0xff) << 24);
}
__device__ __forceinline__ void cp16(unsigned dst, const void* src, unsigned sz) {
    asm volatile("cp.async.cg.shared.global [%0], [%1], 16, %2;"
                 :: "r"(dst), "l"(src), "r"(sz) : "memory");
}
__device__ __forceinline__ void cp_commit() {
    asm volatile("cp.async.commit_group;" ::: "memory");
}
__device__ __forceinline__ void cp_wait0() {
    asm volatile("cp.async.wait_group 0;" ::: "memory");
}

// ---------------------------------------------------------------------------
// Kernel 1: global average pool. 1024 blocks.
// ---------------------------------------------------------------------------
__global__ void gap_kernel(const float* __restrict__ x) {
    const int bc = blockIdx.x;
    const float4* xp = reinterpret_cast<const float4*>(x) + (size_t)bc * (SPAT / 4);
    float s = 0.f;
    for (int i = threadIdx.x; i < SPAT / 4; i += 256) {
        float4 v = xp[i];
        s += (v.x + v.y) + (v.z + v.w);
    }
    #pragma unroll
    for (int o = 16; o > 0; o >>= 1) s += __shfl_xor_sync(0xffffffffu, s, o);
    __shared__ float red[8];
    if ((threadIdx.x & 31) == 0) red[threadIdx.x >> 5] = s;
    __syncthreads();
    if (threadIdx.x < 8) {
        float v = red[threadIdx.x];
        #pragma unroll
        for (int o = 4; o > 0; o >>= 1) v += __shfl_xor_sync(0xffu, v, o);
        if (threadIdx.x == 0) d_gap[bc] = v * (1.0f / (float)SPAT);
    }
}

// ---------------------------------------------------------------------------
// Kernel 2: reduce FC + fc1 + sigmoid. Single block.
// ---------------------------------------------------------------------------
__global__ void fc_kernel(const float* __restrict__ w_reduce,
                          const float* __restrict__ b_reduce,
                          const float* __restrict__ w_fc1,
                          const float* __restrict__ b_fc1) {
    __shared__ float sg[B_ * 16];
    const int tid = threadIdx.x;
    if (tid < B_ * 16) {
        int b = tid >> 4, j = tid & 15;
        float s = b_reduce[j];
        #pragma unroll 4
        for (int i = 0; i < 64; i++) s += d_gap[b * 64 + i] * w_reduce[j * 64 + i];
        sg[b * 16 + j] = s;
    }
    __syncthreads();
    for (int idx = tid; idx < B_ * 128; idx += 256) {
        int b = idx >> 7, c = idx & 127;
        float s = b_fc1[c];
        #pragma unroll
        for (int i = 0; i < 16; i++) s += sg[b * 16 + i] * w_fc1[c * 16 + i];
        d_h[idx] = 1.0f / (1.0f + expf(-s));
    }
}

// ---------------------------------------------------------------------------
// Kernel 3: dynamic weights -> s8 k32 a-fragment layout (hi and lo terms).
//   a-frag m16n8k32.row: reg r -> row = lane/4 + (r&1)*8,
//                        k-base = 4*(lane%3..) + (r>>1)*16, 4 bytes = k..k+3
// ---------------------------------------------------------------------------
__global__ void wdyn_kernel(const float* __restrict__ w_fc2) {
    const int idx = blockIdx.x * blockDim.x + threadIdx.x;
    const int total = B_ * 2 * 27 * 2 * 4 * 32;   // 221184
    if (idx >= total) return;
    const int lane = idx & 31;
    const int mt   = (idx >> 5) & 3;
    const int term = (idx >> 7) & 1;
    int q = idx >> 8;
    const int tap = q % 27;  q /= 27;
    const int g   = q & 1;
    const int b   = q >> 1;

    unsigned r32[4];
    #pragma unroll
    for (int r = 0; r < 4; r++) {
        const int row = (lane >> 2) + (r & 1) * 8;
        const int kb  = 4 * (lane & 3) + (r >> 1) * 16;
        const int oc  = mt * 16 + row;
        int e[4];
        #pragma unroll
        for (int j = 0; j < 4; j++) {
            const int ic = g * 32 + kb + j;
            const float v = w_fc2[oc * 1728 + ic * 27 + tap] *
                            d_h[b * 128 + oc * 2 + (ic >= 32 ? 1 : 0)];
            int h8, l8;
            quant_w(v, h8, l8);
            e[j] = term == 0 ? h8 : l8;
        }
        r32[r] = pack4(e[0], e[1], e[2], e[3]);
    }
    d_wfrag[idx] = make_uint4(r32[0], r32[1], r32[2], r32[3]);
}

// ---------------------------------------------------------------------------
// Kernel 3b: x pre-pass. One thread per scratch row (b,g,t,h,j):
// quantizes 32 ic f32 -> int8 hi/lo, writes two 16B halves. W-halo pre-zeroed.
// ---------------------------------------------------------------------------
__global__ void prepass_kernel(const float* __restrict__ x) {
    const int i = blockIdx.x * 256 + threadIdx.x;
    if (i >= PR2_ROWS) return;
    int j = i % WP;  int q = i / WP;
    int h = q % H_;  q /= H_;
    int t = q % T_;  q /= T_;
    int g = q & 1;
    int b = q >> 1;

    unsigned hh[8] = {0,0,0,0,0,0,0,0}, ll[8] = {0,0,0,0,0,0,0,0};
    const int gw = j - 1;
    if ((unsigned)gw < (unsigned)W_) {
        const float* p = x + ((size_t)(b * C_ + g * 32) * T_ + t) * TH_STRIDE +
                         h * W_ + gw;
        #pragma unroll
        for (int k = 0; k < 8; k++) {
            int h4[4], l4[4];
            #pragma unroll
            for (int c = 0; c < 4; c++) {
                float v = __ldg(p + (size_t)(4 * k + c) * SPAT);
                quant_x(v, h4[c], l4[c]);
            }
            hh[k] = pack4(h4[0], h4[1], h4[2], h4[3]);
            ll[k] = pack4(l4[0], l4[1], l4[2], l4[3]);
        }
    }
    d_xh[(size_t)i * 2]     = make_uint4(hh[0], hh[1], hh[2], hh[3]);
    d_xh[(size_t)i * 2 + 1] = make_uint4(hh[4], hh[5], hh[6], hh[7]);
    d_xl[(size_t)i * 2]     = make_uint4(ll[0], ll[1], ll[2], ll[3]);
    d_xl[(size_t)i * 2 + 1] = make_uint4(ll[4], ll[5], ll[6], ll[7]);
}

// ---------------------------------------------------------------------------
// Kernel 4: implicit-GEMM conv via mma.sync s8 k32, 4-term two-level quant.
// 256 thr, 8 warps = (h-row: wid>>1) x (m-half: wid&1); warp = m32 x n48.
// 3 integer accumulator sets by scale: HH, HL+LH, LL.
// cp.async double-buffered slabs over g in {0,1} (32 ic each).
// ---------------------------------------------------------------------------
extern __shared__ char smem[];

__global__ void __launch_bounds__(NTHR, 1)
conv_kernel(float* __restrict__ out) {
    const int t  = blockIdx.x;
    const int h0 = blockIdx.y * HH;
    const int b  = blockIdx.z;
    const int tid = threadIdx.x;
    const int wid = tid >> 5;
    const int lane = tid & 31;
    const int hrow = wid >> 1;      // 0..3
    const int mhalf = wid & 1;      // 0..1

    const unsigned sb = smem_u32(smem);

    int acc1[2][6][4], acc2[2][6][4], acc3[2][6][4];
    #pragma unroll
    for (int mt = 0; mt < 2; mt++)
        #pragma unroll
        for (int nt = 0; nt < 6; nt++)
            #pragma unroll
            for (int k = 0; k < 4; k++) {
                acc1[mt][nt][k] = 0; acc2[mt][nt][k] = 0; acc3[mt][nt][k] = 0;
            }

    // ldmatrix lane address components
    const int rb_off = (lane & 7) + ((lane >> 4) & 1) * 8;
    const int bhalf  = (lane >> 3) & 1;

    // ---- prefetch: fill buffer `buf` with group `g` slabs (zfill halo) ----
    auto prefetch = [&](int g, int buf) {
        const char* xh8 = reinterpret_cast<const char*>(d_xh);
        const char* xl8 = reinterpret_cast<const char*>(d_xl);
        #pragma unroll 1
        for (int i = tid; i < 2 * ROWS * 2; i += NTHR) {   // 3456 16B ops
            const int term = i >= 2 * ROWS;
            const int rem  = term ? i - 2 * ROWS : i;
            const int r  = rem >> 1;
            const int hb = rem & 1;
            int t2 = r / (HP * WP);
            int rr = r - t2 * (HP * WP);
            int hp = rr / WP;
            int wp = rr - hp * WP;
            const int gt = t + t2 - 1, gh = h0 + hp - 1;
            const unsigned ok =
                (((unsigned)gt < (unsigned)T_) & ((unsigned)gh < (unsigned)H_))
                ? 16u : 0u;
            const int gtc = gt < 0 ? 0 : (gt >= T_ ? T_ - 1 : gt);
            const int ghc = gh < 0 ? 0 : (gh >= H_ ? H_ - 1 : gh);
            const size_t srow =
                ((((size_t)(b * 2 + g) * T_ + gtc) * H_ + ghc) * WP + wp);
            const char* src = (term ? xl8 : xh8) + srow * 32 + hb * 16;
            const unsigned dst = sb + buf * BUFB + term * SLABB + r * 32 +
                                 ((((r >> 2) & 1) ^ hb) << 4);
            cp16(dst, src, ok);
        }
        cp_commit();
    };

    prefetch(0, 0);

    // W-fragment base: [b][g][tap][term:2][mt:4][lane]; per-tap stride 256 uint4
    const uint4* wf0 = d_wfrag + (size_t)(b * 2) * 27 * 256 + lane;
    auto wptr = [&](int k) { return wf0 + (size_t)k * 256; };  // k = g*27+tap

    // preload W fragments for k=0 (this warp's 2 m-tiles, hi+lo terms)
    uint4 whc[2], wlc[2];
    {
        const uint4* wt = wptr(0);
        #pragma unroll
        for (int mt = 0; mt < 2; mt++) {
            const int mtg = mhalf * 2 + mt;
            whc[mt] = __ldg(wt + mtg * 32);          // term 0 (hi)
            wlc[mt] = __ldg(wt + 128 + mtg * 32);    // term 1 (lo)
        }
    }

    #pragma unroll 1
    for (int g = 0; g < 2; g++) {
        cp_wait0();
        __syncthreads();
        if (g < 1) prefetch(g + 1, (g + 1) & 1);

        const unsigned sl_h = sb + (g & 1) * BUFB;
        const unsigned sl_l = sl_h + SLABB;

        #pragma unroll 1
        for (int tap = 0; tap < 27; tap++) {
            // ---- prefetch next tap's W fragments ----
            const int kf = g * 27 + tap;
            const uint4* wt = wptr(kf < 53 ? kf + 1 : 53);
            uint4 whn[2], wln[2];
            #pragma unroll
            for (int mt = 0; mt < 2; mt++) {
                const int mtg = mhalf * 2 + mt;
                whn[mt] = __ldg(wt + mtg * 32);
                wln[mt] = __ldg(wt + 128 + mtg * 32);
            }

            // ---- B fragments (Xh, Xl) for current tap ----
            const int dt2 = tap / 9;
            const int rem = tap - dt2 * 9;
            const int dh  = rem / 3;
            const int dw  = rem - dh * 3;
            const int shift = (dt2 * HP + dh) * WP + dw;

            unsigned bh[12], bl[12];
            #pragma unroll
            for (int q = 0; q < 3; q++) {
                int r = hrow * 48 + q * 16 + rb_off + shift;
                unsigned a = r * 32 + (((((r >> 2) & 1) ^ bhalf)) << 4);
                ldmx4(bh[q * 4], bh[q * 4 + 1], bh[q * 4 + 2], bh[q * 4 + 3],
                      sl_h + a);
                ldmx4(bl[q * 4], bl[q * 4 + 1], bl[q * 4 + 2], bl[q * 4 + 3],
                      sl_l + a);
            }

            // ---- 4 term groups into 3 scale-matched accumulator sets ----
            // HH -> acc1
            #pragma unroll
            for (int mt = 0; mt < 2; mt++)
                #pragma unroll
                for (int nt = 0; nt < 6; nt++) {
                    const int q = nt >> 1, pr = (nt & 1) * 2;
                    mma_s8(acc1[mt][nt], whc[mt],
                           bh[q * 4 + pr], bh[q * 4 + pr + 1]);
                }
            // HL (Wh*Xl) -> acc2
            #pragma unroll
            for (int mt = 0; mt < 2; mt++)
                #pragma unroll
                for (int nt = 0; nt < 6; nt++) {
                    const int q = nt >> 1, pr = (nt & 1) * 2;
                    mma_s8(acc2[mt][nt], whc[mt],
                           bl[q * 4 + pr], bl[q * 4 + pr + 1]);
                }
            // LH (Wl*Xh) -> acc2
            #pragma unroll
            for (int mt = 0; mt < 2; mt++)
                #pragma unroll
                for (int nt = 0; nt < 6; nt++) {
                    const int q = nt >> 1, pr = (nt & 1) * 2;
                    mma_s8(acc2[mt][nt], wlc[mt],
                           bh[q * 4 + pr], bh[q * 4 + pr + 1]);
                }
            // LL (Wl*Xl) -> acc3
            #pragma unroll
            for (int mt = 0; mt < 2; mt++)
                #pragma unroll
                for (int nt = 0; nt < 6; nt++) {
                    const int q = nt >> 1, pr = (nt & 1) * 2;
                    mma_s8(acc3[mt][nt], wlc[mt],
                           bl[q * 4 + pr], bl[q * 4 + pr + 1]);
                }

            // ---- rotate W pipeline ----
            #pragma unroll
            for (int mt = 0; mt < 2; mt++) {
                whc[mt] = whn[mt];
                wlc[mt] = wln[mt];
            }
        }
    }

    // ---- epilogue: out = 2^-14 (acc1 + acc2/128 + acc3/16384) ----
    const int gh = h0 + hrow;
    #pragma unroll
    for (int mt = 0; mt < 2; mt++) {
        const int oc0 = mhalf * 32 + mt * 16 + (lane >> 2);
        #pragma unroll
        for (int nt = 0; nt < 6; nt++) {
            const int wc = nt * 8 + 2 * (lane & 3);
            if (wc < W_) {
                float v[4];
                #pragma unroll
                for (int k = 0; k < 4; k++) {
                    v[k] = ((float)acc1[mt][nt][k] +
                            (float)acc2[mt][nt][k] * 0.0078125f +
                            (float)acc3[mt][nt][k] * 6.103515625e-05f) *
                           6.103515625e-05f;
                }
                size_t o0 = ((size_t)(b * C_ + oc0) * T_ + t) * TH_STRIDE +
                            gh * W_ + wc;
                size_t o1 = o0 + (size_t)8 * SPAT;   // oc0+8
                *(float2*)(out + o0) = make_float2(v[0], v[1]);
                *(float2*)(out + o1) = make_float2(v[2], v[3]);
            }
        }
    }
}

// ---------------------------------------------------------------------------
extern "C" void kernel_launch(void* const* d_in, const int* in_sizes, int n_in,
                              void* d_out, int out_size) {
    const float* x        = (const float*)d_in[0];
    const float* w_reduce = (const float*)d_in[1];
    const float* b_reduce = (const float*)d_in[2];
    const float* w_fc1    = (const float*)d_in[3];
    const float* b_fc1    = (const float*)d_in[4];
    const float* w_fc2    = (const float*)d_in[5];
    float* out = (float*)d_out;

    cudaFuncSetAttribute(conv_kernel,
                         cudaFuncAttributeMaxDynamicSharedMemorySize, SM_TOTAL);

    gap_kernel<<<B_ * C_, 256>>>(x);
    fc_kernel<<<1, 256>>>(w_reduce, b_reduce, w_fc1, b_fc1);
    {
        const int total = B_ * 2 * 27 * 2 * 4 * 32;
        wdyn_kernel<<<(total + 255) / 256, 256>>>(w_fc2);
    }
    prepass_kernel<<<(PR2_ROWS + 255) / 256, 256>>>(x);
    {
        dim3 grid(T_, H_ / HH, B_);   // (30, 16, 16) = 7680 blocks
        conv_kernel<<<grid, NTHR, SM_TOTAL>>>(out);
    }
}

// round 16
// speedup vs baseline: 1.8096x; 1.1202x over previous
#include <cuda_runtime.h>
#include <cstdint>
#include <cstddef>

// ---------------------------------------------------------------------------
// Problem constants
// ---------------------------------------------------------------------------
#define B_   16
#define C_   64
#define T_   30
#define H_   64
#define W_   44
#define SPAT (T_ * H_ * W_)        // 84480
#define TH_STRIDE (H_ * W_)        // 2816

// conv tiling
#define HH 4                       // output h rows per block
#define HP 6                       // h rows incl halo
#define WP 48                      // padded w per row
#define ROWS (3 * HP * WP)         // 864 pixel rows per slab
#define ROWSP 880                  // padded rows (ldmatrix tap-shift bleed, max r=865)
#define SLABB (ROWSP * 32)         // 28160 B per term slab (32 int8 ic per row)
#define BUFB  (2 * SLABB)          // 56320 B per buffer (Xh + Xl)
#define SM_TOTAL (2 * BUFB)        // 112640 B (double buffered)

#define NTHR 256                   // 8 warps: (h-row 0..3) x (m-half 0..1)

#define PR2_ROWS (B_ * 2 * T_ * H_ * WP)   // 2,949,120 scratch rows (2 ic-groups of 32)

// quant scales: x = 2^-4 (Xh + Xl/128), w = 2^-10 (Wh + Wl/128)
// out = 2^-14 * (acc_HH + acc_HLLH/128)          [LL term dropped: ~4e-4]

// Scratch (static device globals; no allocation)
__device__ float d_gap[B_ * C_];
__device__ float d_h[B_ * 128];
// W fragments, s8 k32 a-frag lane order: [b][g:2][tap:27][term:2][mt:4][lane:32] uint4
__device__ uint4 d_wfrag[B_ * 2 * 27 * 2 * 4 * 32];
// x int8 hi/lo scratch, smem-row layout: [b][g:2][t][h][j:48] rows of 32B (32 ic)
__device__ uint4 d_xh[PR2_ROWS * 2];
__device__ uint4 d_xl[PR2_ROWS * 2];

// ---------------------------------------------------------------------------
// helpers
// ---------------------------------------------------------------------------
__device__ __forceinline__ unsigned smem_u32(const void* p) {
    unsigned a;
    asm("{ .reg .u64 t; cvta.to.shared.u64 t, %1; cvt.u32.u64 %0, t; }"
        : "=r"(a) : "l"(p));
    return a;
}
__device__ __forceinline__ void ldmx4(unsigned& r0, unsigned& r1,
                                      unsigned& r2, unsigned& r3, unsigned a) {
    asm volatile("ldmatrix.sync.aligned.m8n8.x4.shared.b16 {%0,%1,%2,%3}, [%4];"
                 : "=r"(r0), "=r"(r1), "=r"(r2), "=r"(r3) : "r"(a));
}
__device__ __forceinline__ void mma_s8(int* c, const uint4 a,
                                       unsigned b0, unsigned b1) {
    asm volatile(
        "mma.sync.aligned.m16n8k32.row.col.s32.s8.s8.s32 "
        "{%0,%1,%2,%3}, {%4,%5,%6,%7}, {%8,%9}, {%0,%1,%2,%3};"
        : "+r"(c[0]), "+r"(c[1]), "+r"(c[2]), "+r"(c[3])
        : "r"(a.x), "r"(a.y), "r"(a.z), "r"(a.w), "r"(b0), "r"(b1));
}
__device__ __forceinline__ int q8clamp(float v) {
    int i = __float2int_rn(v);
    return i < -127 ? -127 : (i > 127 ? 127 : i);
}
// quantize v*16 -> (hi, lo): v ~ (hi + lo/128) / 16
__device__ __forceinline__ void quant_x(float v, int& h, int& l) {
    float s = v * 16.0f;
    h = q8clamp(s);
    l = q8clamp((s - (float)h) * 128.0f);
}
// quantize w*1024 -> (hi, lo): w ~ (hi + lo/128) / 1024
__device__ __forceinline__ void quant_w(float v, int& h, int& l) {
    float s = v * 1024.0f;
    h = q8clamp(s);
    l = q8clamp((s - (float)h) * 128.0f);
}
__device__ __forceinline__ unsigned pack4(int a, int b, int c, int d) {
    return (unsigned)(a & 0xff) | ((unsigned)(b & 0xff) << 8) |
           ((unsigned)(c & 0xff) << 16) | ((unsigned)(d & 0xff) << 24);
}
__device__ __forceinline__ void cp16(unsigned dst, const void* src, unsigned sz) {
    asm volatile("cp.async.cg.shared.global [%0], [%1], 16, %2;"
                 :: "r"(dst), "l"(src), "r"(sz) : "memory");
}
__device__ __forceinline__ void cp_commit() {
    asm volatile("cp.async.commit_group;" ::: "memory");
}
__device__ __forceinline__ void cp_wait0() {
    asm volatile("cp.async.wait_group 0;" ::: "memory");
}

// ---------------------------------------------------------------------------
// Kernel 1: global average pool. 1024 blocks.
// ---------------------------------------------------------------------------
__global__ void gap_kernel(const float* __restrict__ x) {
    const int bc = blockIdx.x;
    const float4* xp = reinterpret_cast<const float4*>(x) + (size_t)bc * (SPAT / 4);
    float s = 0.f;
    for (int i = threadIdx.x; i < SPAT / 4; i += 256) {
        float4 v = xp[i];
        s += (v.x + v.y) + (v.z + v.w);
    }
    #pragma unroll
    for (int o = 16; o > 0; o >>= 1) s += __shfl_xor_sync(0xffffffffu, s, o);
    __shared__ float red[8];
    if ((threadIdx.x & 31) == 0) red[threadIdx.x >> 5] = s;
    __syncthreads();
    if (threadIdx.x < 8) {
        float v = red[threadIdx.x];
        #pragma unroll
        for (int o = 4; o > 0; o >>= 1) v += __shfl_xor_sync(0xffu, v, o);
        if (threadIdx.x == 0) d_gap[bc] = v * (1.0f / (float)SPAT);
    }
}

// ---------------------------------------------------------------------------
// Kernel 2: reduce FC + fc1 + sigmoid. Single block.
// ---------------------------------------------------------------------------
__global__ void fc_kernel(const float* __restrict__ w_reduce,
                          const float* __restrict__ b_reduce,
                          const float* __restrict__ w_fc1,
                          const float* __restrict__ b_fc1) {
    __shared__ float sg[B_ * 16];
    const int tid = threadIdx.x;
    if (tid < B_ * 16) {
        int b = tid >> 4, j = tid & 15;
        float s = b_reduce[j];
        #pragma unroll 4
        for (int i = 0; i < 64; i++) s += d_gap[b * 64 + i] * w_reduce[j * 64 + i];
        sg[b * 16 + j] = s;
    }
    __syncthreads();
    for (int idx = tid; idx < B_ * 128; idx += 256) {
        int b = idx >> 7, c = idx & 127;
        float s = b_fc1[c];
        #pragma unroll
        for (int i = 0; i < 16; i++) s += sg[b * 16 + i] * w_fc1[c * 16 + i];
        d_h[idx] = 1.0f / (1.0f + expf(-s));
    }
}

// ---------------------------------------------------------------------------
// Kernel 3: dynamic weights -> s8 k32 a-fragment layout (hi and lo terms).
// ---------------------------------------------------------------------------
__global__ void wdyn_kernel(const float* __restrict__ w_fc2) {
    const int idx = blockIdx.x * blockDim.x + threadIdx.x;
    const int total = B_ * 2 * 27 * 2 * 4 * 32;   // 221184
    if (idx >= total) return;
    const int lane = idx & 31;
    const int mt   = (idx >> 5) & 3;
    const int term = (idx >> 7) & 1;
    int q = idx >> 8;
    const int tap = q % 27;  q /= 27;
    const int g   = q & 1;
    const int b   = q >> 1;

    unsigned r32[4];
    #pragma unroll
    for (int r = 0; r < 4; r++) {
        const int row = (lane >> 2) + (r & 1) * 8;
        const int kb  = 4 * (lane & 3) + (r >> 1) * 16;
        const int oc  = mt * 16 + row;
        int e[4];
        #pragma unroll
        for (int j = 0; j < 4; j++) {
            const int ic = g * 32 + kb + j;
            const float v = w_fc2[oc * 1728 + ic * 27 + tap] *
                            d_h[b * 128 + oc * 2 + (ic >= 32 ? 1 : 0)];
            int h8, l8;
            quant_w(v, h8, l8);
            e[j] = term == 0 ? h8 : l8;
        }
        r32[r] = pack4(e[0], e[1], e[2], e[3]);
    }
    d_wfrag[idx] = make_uint4(r32[0], r32[1], r32[2], r32[3]);
}

// ---------------------------------------------------------------------------
// Kernel 3b: x pre-pass. One thread per scratch row (b,g,t,h,j):
// quantizes 32 ic f32 -> int8 hi/lo, writes two 16B halves. W-halo pre-zeroed.
// ---------------------------------------------------------------------------
__global__ void prepass_kernel(const float* __restrict__ x) {
    const int i = blockIdx.x * 256 + threadIdx.x;
    if (i >= PR2_ROWS) return;
    int j = i % WP;  int q = i / WP;
    int h = q % H_;  q /= H_;
    int t = q % T_;  q /= T_;
    int g = q & 1;
    int b = q >> 1;

    unsigned hh[8] = {0,0,0,0,0,0,0,0}, ll[8] = {0,0,0,0,0,0,0,0};
    const int gw = j - 1;
    if ((unsigned)gw < (unsigned)W_) {
        const float* p = x + ((size_t)(b * C_ + g * 32) * T_ + t) * TH_STRIDE +
                         h * W_ + gw;
        #pragma unroll
        for (int k = 0; k < 8; k++) {
            int h4[4], l4[4];
            #pragma unroll
            for (int c = 0; c < 4; c++) {
                float v = __ldg(p + (size_t)(4 * k + c) * SPAT);
                quant_x(v, h4[c], l4[c]);
            }
            hh[k] = pack4(h4[0], h4[1], h4[2], h4[3]);
            ll[k] = pack4(l4[0], l4[1], l4[2], l4[3]);
        }
    }
    d_xh[(size_t)i * 2]     = make_uint4(hh[0], hh[1], hh[2], hh[3]);
    d_xh[(size_t)i * 2 + 1] = make_uint4(hh[4], hh[5], hh[6], hh[7]);
    d_xl[(size_t)i * 2]     = make_uint4(ll[0], ll[1], ll[2], ll[3]);
    d_xl[(size_t)i * 2 + 1] = make_uint4(ll[4], ll[5], ll[6], ll[7]);
}

// ---------------------------------------------------------------------------
// Kernel 4: implicit-GEMM conv via mma.sync s8 k32, 3-term two-level quant
// (HH; HL+LH; LL dropped). 256 thr, 8 warps = (h-row) x (m-half);
// warp = m32 x n48. cp.async double-buffered slabs over g in {0,1}.
// ---------------------------------------------------------------------------
extern __shared__ char smem[];

__global__ void __launch_bounds__(NTHR, 1)
conv_kernel(float* __restrict__ out) {
    const int t  = blockIdx.x;
    const int h0 = blockIdx.y * HH;
    const int b  = blockIdx.z;
    const int tid = threadIdx.x;
    const int wid = tid >> 5;
    const int lane = tid & 31;
    const int hrow = wid >> 1;      // 0..3
    const int mhalf = wid & 1;      // 0..1

    const unsigned sb = smem_u32(smem);

    int acc1[2][6][4], acc2[2][6][4];
    #pragma unroll
    for (int mt = 0; mt < 2; mt++)
        #pragma unroll
        for (int nt = 0; nt < 6; nt++)
            #pragma unroll
            for (int k = 0; k < 4; k++) {
                acc1[mt][nt][k] = 0; acc2[mt][nt][k] = 0;
            }

    // ldmatrix lane address components
    const int rb_off = (lane & 7) + ((lane >> 4) & 1) * 8;
    const int bhalf  = (lane >> 3) & 1;

    // ---- prefetch: fill buffer `buf` with group `g` slabs (zfill halo) ----
    auto prefetch = [&](int g, int buf) {
        const char* xh8 = reinterpret_cast<const char*>(d_xh);
        const char* xl8 = reinterpret_cast<const char*>(d_xl);
        #pragma unroll 1
        for (int i = tid; i < 2 * ROWS * 2; i += NTHR) {   // 3456 16B ops
            const int term = i >= 2 * ROWS;
            const int rem  = term ? i - 2 * ROWS : i;
            const int r  = rem >> 1;
            const int hb = rem & 1;
            int t2 = r / (HP * WP);
            int rr = r - t2 * (HP * WP);
            int hp = rr / WP;
            int wp = rr - hp * WP;
            const int gt = t + t2 - 1, gh = h0 + hp - 1;
            const unsigned ok =
                (((unsigned)gt < (unsigned)T_) & ((unsigned)gh < (unsigned)H_))
                ? 16u : 0u;
            const int gtc = gt < 0 ? 0 : (gt >= T_ ? T_ - 1 : gt);
            const int ghc = gh < 0 ? 0 : (gh >= H_ ? H_ - 1 : gh);
            const size_t srow =
                ((((size_t)(b * 2 + g) * T_ + gtc) * H_ + ghc) * WP + wp);
            const char* src = (term ? xl8 : xh8) + srow * 32 + hb * 16;
            const unsigned dst = sb + buf * BUFB + term * SLABB + r * 32 +
                                 ((((r >> 2) & 1) ^ hb) << 4);
            cp16(dst, src, ok);
        }
        cp_commit();
    };

    prefetch(0, 0);

    // W-fragment base: [b][g][tap][term:2][mt:4][lane]; per-tap stride 256 uint4
    const uint4* wf0 = d_wfrag + (size_t)(b * 2) * 27 * 256 + lane;
    auto wptr = [&](int k) { return wf0 + (size_t)k * 256; };  // k = g*27+tap

    // preload W fragments for k=0 (this warp's 2 m-tiles, hi+lo terms)
    uint4 whc[2], wlc[2];
    {
        const uint4* wt = wptr(0);
        #pragma unroll
        for (int mt = 0; mt < 2; mt++) {
            const int mtg = mhalf * 2 + mt;
            whc[mt] = __ldg(wt + mtg * 32);          // term 0 (hi)
            wlc[mt] = __ldg(wt + 128 + mtg * 32);    // term 1 (lo)
        }
    }

    #pragma unroll 1
    for (int g = 0; g < 2; g++) {
        cp_wait0();
        __syncthreads();
        if (g < 1) prefetch(g + 1, (g + 1) & 1);

        const unsigned sl_h = sb + (g & 1) * BUFB;
        const unsigned sl_l = sl_h + SLABB;

        #pragma unroll 1
        for (int tap = 0; tap < 27; tap++) {
            // ---- prefetch next tap's W fragments ----
            const int kf = g * 27 + tap;
            const uint4* wt = wptr(kf < 53 ? kf + 1 : 53);
            uint4 whn[2], wln[2];
            #pragma unroll
            for (int mt = 0; mt < 2; mt++) {
                const int mtg = mhalf * 2 + mt;
                whn[mt] = __ldg(wt + mtg * 32);
                wln[mt] = __ldg(wt + 128 + mtg * 32);
            }

            // ---- B fragments (Xh, Xl) for current tap ----
            const int dt2 = tap / 9;
            const int rem = tap - dt2 * 9;
            const int dh  = rem / 3;
            const int dw  = rem - dh * 3;
            const int shift = (dt2 * HP + dh) * WP + dw;

            unsigned bh[12], bl[12];
            #pragma unroll
            for (int q = 0; q < 3; q++) {
                int r = hrow * 48 + q * 16 + rb_off + shift;
                unsigned a = r * 32 + (((((r >> 2) & 1) ^ bhalf)) << 4);
                ldmx4(bh[q * 4], bh[q * 4 + 1], bh[q * 4 + 2], bh[q * 4 + 3],
                      sl_h + a);
                ldmx4(bl[q * 4], bl[q * 4 + 1], bl[q * 4 + 2], bl[q * 4 + 3],
                      sl_l + a);
            }

            // ---- 3 term groups into 2 scale-matched accumulator sets ----
            // HH -> acc1
            #pragma unroll
            for (int mt = 0; mt < 2; mt++)
                #pragma unroll
                for (int nt = 0; nt < 6; nt++) {
                    const int q = nt >> 1, pr = (nt & 1) * 2;
                    mma_s8(acc1[mt][nt], whc[mt],
                           bh[q * 4 + pr], bh[q * 4 + pr + 1]);
                }
            // HL (Wh*Xl) -> acc2
            #pragma unroll
            for (int mt = 0; mt < 2; mt++)
                #pragma unroll
                for (int nt = 0; nt < 6; nt++) {
                    const int q = nt >> 1, pr = (nt & 1) * 2;
                    mma_s8(acc2[mt][nt], whc[mt],
                           bl[q * 4 + pr], bl[q * 4 + pr + 1]);
                }
            // LH (Wl*Xh) -> acc2
            #pragma unroll
            for (int mt = 0; mt < 2; mt++)
                #pragma unroll
                for (int nt = 0; nt < 6; nt++) {
                    const int q = nt >> 1, pr = (nt & 1) * 2;
                    mma_s8(acc2[mt][nt], wlc[mt],
                           bh[q * 4 + pr], bh[q * 4 + pr + 1]);
                }

            // ---- rotate W pipeline ----
            #pragma unroll
            for (int mt = 0; mt < 2; mt++) {
                whc[mt] = whn[mt];
                wlc[mt] = wln[mt];
            }
        }
    }

    // ---- epilogue: out = 2^-14 (acc1 + acc2/128) ----
    const int gh = h0 + hrow;
    #pragma unroll
    for (int mt = 0; mt < 2; mt++) {
        const int oc0 = mhalf * 32 + mt * 16 + (lane >> 2);
        #pragma unroll
        for (int nt = 0; nt < 6; nt++) {
            const int wc = nt * 8 + 2 * (lane & 3);
            if (wc < W_) {
                float v[4];
                #pragma unroll
                for (int k = 0; k < 4; k++) {
                    v[k] = ((float)acc1[mt][nt][k] +
                            (float)acc2[mt][nt][k] * 0.0078125f) *
                           6.103515625e-05f;
                }
                size_t o0 = ((size_t)(b * C_ + oc0) * T_ + t) * TH_STRIDE +
                            gh * W_ + wc;
                size_t o1 = o0 + (size_t)8 * SPAT;   // oc0+8
                *(float2*)(out + o0) = make_float2(v[0], v[1]);
                *(float2*)(out + o1) = make_float2(v[2], v[3]);
            }
        }
    }
}

// ---------------------------------------------------------------------------
extern "C" void kernel_launch(void* const* d_in, const int* in_sizes, int n_in,
                              void* d_out, int out_size) {
    const float* x        = (const float*)d_in[0];
    const float* w_reduce = (const float*)d_in[1];
    const float* b_reduce = (const float*)d_in[2];
    const float* w_fc1    = (const float*)d_in[3];
    const float* b_fc1    = (const float*)d_in[4];
    const float* w_fc2    = (const float*)d_in[5];
    float* out = (float*)d_out;

    cudaFuncSetAttribute(conv_kernel,
                         cudaFuncAttributeMaxDynamicSharedMemorySize, SM_TOTAL);

    gap_kernel<<<B_ * C_, 256>>>(x);
    fc_kernel<<<1, 256>>>(w_reduce, b_reduce, w_fc1, b_fc1);
    {
        const int total = B_ * 2 * 27 * 2 * 4 * 32;
        wdyn_kernel<<<(total + 255) / 256, 256>>>(w_fc2);
    }
    prepass_kernel<<<(PR2_ROWS + 255) / 256, 256>>>(x);
    {
        dim3 grid(T_, H_ / HH, B_);   // (30, 16, 16) = 7680 blocks
        conv_kernel<<<grid, NTHR, SM_TOTAL>>>(out);
    }
}

// round 17
// speedup vs baseline: 2.6569x; 1.4682x over previous
#include <cuda_runtime.h>
#include <cuda_fp16.h>
#include <cstdint>
#include <cstddef>

// ---------------------------------------------------------------------------
// Problem constants
// ---------------------------------------------------------------------------
#define B_   16
#define C_   64
#define T_   30
#define H_   64
#define W_   44
#define SPAT (T_ * H_ * W_)        // 84480
#define TH_STRIDE (H_ * W_)        // 2816

// conv tiling
#define HH 4                       // output h rows per block
#define HP 6                       // h rows incl halo
#define WP 48                      // padded w per row
#define ROWS (3 * HP * WP)         // 864 pixel rows per slab
#define ROWSP 880                  // padded rows (ldmatrix tap-shift bleed, max r=865)
#define BUFB (ROWSP * 64)          // 56320 B per buffer (64B fp16 rows: 32 ic)
#define SM_TOTAL (2 * BUFB)        // 112640 B (double buffered)

#define NTHR 256                   // 8 warps: (h-row 0..3) x (m-half 0..1)

#define PR2_ROWS (B_ * 2 * T_ * H_ * WP)   // 2,949,120 scratch rows (2 ic-groups of 32)

// Scratch (static device globals; no allocation)
__device__ float d_gap[B_ * C_];
__device__ float d_h[B_ * 128];
// W fragments, f16 k16 a-frag lane order: [b][g:2][tap:27][ks:2][mt:4][lane:32] uint4
__device__ uint4 d_wfrag[B_ * 2 * 27 * 2 * 4 * 32];
// x fp16 scratch, smem-row layout: [b][g:2][t][h][j:48] rows of 64B (32 ic halves)
__device__ uint4 d_xf[(size_t)PR2_ROWS * 4];

// ---------------------------------------------------------------------------
// helpers
// ---------------------------------------------------------------------------
__device__ __forceinline__ unsigned smem_u32(const void* p) {
    unsigned a;
    asm("{ .reg .u64 t; cvta.to.shared.u64 t, %1; cvt.u32.u64 %0, t; }"
        : "=r"(a) : "l"(p));
    return a;
}
__device__ __forceinline__ void ldmx4(unsigned& r0, unsigned& r1,
                                      unsigned& r2, unsigned& r3, unsigned a) {
    asm volatile("ldmatrix.sync.aligned.m8n8.x4.shared.b16 {%0,%1,%2,%3}, [%4];"
                 : "=r"(r0), "=r"(r1), "=r"(r2), "=r"(r3) : "r"(a));
}
__device__ __forceinline__ void mma_f16(float* c, const uint4 a,
                                        unsigned b0, unsigned b1) {
    asm volatile(
        "mma.sync.aligned.m16n8k16.row.col.f32.f16.f16.f32 "
        "{%0,%1,%2,%3}, {%4,%5,%6,%7}, {%8,%9}, {%0,%1,%2,%3};"
        : "+f"(c[0]), "+f"(c[1]), "+f"(c[2]), "+f"(c[3])
        : "r"(a.x), "r"(a.y), "r"(a.z), "r"(a.w), "r"(b0), "r"(b1));
}
__device__ __forceinline__ unsigned pack_h2(float a, float b) {
    __half2 h = __floats2half2_rn(a, b);
    return *reinterpret_cast<unsigned*>(&h);
}
__device__ __forceinline__ void cp16(unsigned dst, const void* src, unsigned sz) {
    asm volatile("cp.async.cg.shared.global [%0], [%1], 16, %2;"
                 :: "r"(dst), "l"(src), "r"(sz) : "memory");
}
__device__ __forceinline__ void cp_commit() {
    asm volatile("cp.async.commit_group;" ::: "memory");
}
__device__ __forceinline__ void cp_wait0() {
    asm volatile("cp.async.wait_group 0;" ::: "memory");
}

// ---------------------------------------------------------------------------
// Kernel 1: global average pool. 1024 blocks.
// ---------------------------------------------------------------------------
__global__ void gap_kernel(const float* __restrict__ x) {
    const int bc = blockIdx.x;
    const float4* xp = reinterpret_cast<const float4*>(x) + (size_t)bc * (SPAT / 4);
    float s = 0.f;
    for (int i = threadIdx.x; i < SPAT / 4; i += 256) {
        float4 v = xp[i];
        s += (v.x + v.y) + (v.z + v.w);
    }
    #pragma unroll
    for (int o = 16; o > 0; o >>= 1) s += __shfl_xor_sync(0xffffffffu, s, o);
    __shared__ float red[8];
    if ((threadIdx.x & 31) == 0) red[threadIdx.x >> 5] = s;
    __syncthreads();
    if (threadIdx.x < 8) {
        float v = red[threadIdx.x];
        #pragma unroll
        for (int o = 4; o > 0; o >>= 1) v += __shfl_xor_sync(0xffu, v, o);
        if (threadIdx.x == 0) d_gap[bc] = v * (1.0f / (float)SPAT);
    }
}

// ---------------------------------------------------------------------------
// Kernel 2: reduce FC + fc1 + sigmoid. Single block.
// ---------------------------------------------------------------------------
__global__ void fc_kernel(const float* __restrict__ w_reduce,
                          const float* __restrict__ b_reduce,
                          const float* __restrict__ w_fc1,
                          const float* __restrict__ b_fc1) {
    __shared__ float sg[B_ * 16];
    const int tid = threadIdx.x;
    if (tid < B_ * 16) {
        int b = tid >> 4, j = tid & 15;
        float s = b_reduce[j];
        #pragma unroll 4
        for (int i = 0; i < 64; i++) s += d_gap[b * 64 + i] * w_reduce[j * 64 + i];
        sg[b * 16 + j] = s;
    }
    __syncthreads();
    for (int idx = tid; idx < B_ * 128; idx += 256) {
        int b = idx >> 7, c = idx & 127;
        float s = b_fc1[c];
        #pragma unroll
        for (int i = 0; i < 16; i++) s += sg[b * 16 + i] * w_fc1[c * 16 + i];
        d_h[idx] = 1.0f / (1.0f + expf(-s));
    }
}

// ---------------------------------------------------------------------------
// Kernel 3: dynamic weights -> f16 k16 a-fragment layout.
//   a-frag m16n8k16.row: reg r -> row = lane/4 + (r&1)*8,
//                        k = 2*(lane%4) + (r>>1)*8, fp16 pair (k, k+1)
//   ic = g*32 + ks*16 + k + j;  h factor index = oc*2 + g
// ---------------------------------------------------------------------------
__global__ void wdyn_kernel(const float* __restrict__ w_fc2) {
    const int idx = blockIdx.x * blockDim.x + threadIdx.x;
    const int total = B_ * 2 * 27 * 2 * 4 * 32;   // 221184
    if (idx >= total) return;
    const int lane = idx & 31;
    const int mt   = (idx >> 5) & 3;
    const int ks   = (idx >> 7) & 1;
    int q = idx >> 8;
    const int tap = q % 27;  q /= 27;
    const int g   = q & 1;
    const int b   = q >> 1;

    unsigned r32[4];
    #pragma unroll
    for (int r = 0; r < 4; r++) {
        const int row = (lane >> 2) + (r & 1) * 8;
        const int kb  = 2 * (lane & 3) + (r >> 1) * 8;
        const int oc  = mt * 16 + row;
        const float hf = d_h[b * 128 + oc * 2 + g];
        float v[2];
        #pragma unroll
        for (int j = 0; j < 2; j++) {
            const int ic = g * 32 + ks * 16 + kb + j;
            v[j] = w_fc2[oc * 1728 + ic * 27 + tap] * hf;
        }
        r32[r] = pack_h2(v[0], v[1]);
    }
    d_wfrag[idx] = make_uint4(r32[0], r32[1], r32[2], r32[3]);
}

// ---------------------------------------------------------------------------
// Kernel 3b: x pre-pass. One thread per scratch row (b,g,t,h,j):
// converts 32 ic f32 -> fp16, writes 64B row (4x uint4). W-halo pre-zeroed.
// ---------------------------------------------------------------------------
__global__ void prepass_kernel(const float* __restrict__ x) {
    const int i = blockIdx.x * 256 + threadIdx.x;
    if (i >= PR2_ROWS) return;
    int j = i % WP;  int q = i / WP;
    int h = q % H_;  q /= H_;
    int t = q % T_;  q /= T_;
    int g = q & 1;
    int b = q >> 1;

    unsigned e[16];
    #pragma unroll
    for (int k = 0; k < 16; k++) e[k] = 0;
    const int gw = j - 1;
    if ((unsigned)gw < (unsigned)W_) {
        const float* p = x + ((size_t)(b * C_ + g * 32) * T_ + t) * TH_STRIDE +
                         h * W_ + gw;
        #pragma unroll
        for (int k = 0; k < 16; k++) {
            float v0 = __ldg(p + (size_t)(2 * k) * SPAT);
            float v1 = __ldg(p + (size_t)(2 * k + 1) * SPAT);
            e[k] = pack_h2(v0, v1);
        }
    }
    #pragma unroll
    for (int c = 0; c < 4; c++)
        d_xf[(size_t)i * 4 + c] =
            make_uint4(e[4 * c], e[4 * c + 1], e[4 * c + 2], e[4 * c + 3]);
}

// ---------------------------------------------------------------------------
// Kernel 4: implicit-GEMM conv via mma.sync f16 k16, SINGLE PASS.
// 256 thr, 8 warps = (h-row: wid>>1) x (m-half: wid&1); warp = m32 x n48.
// Slab rows = 64B (32 fp16 ic), swizzle: chunk c -> c ^ ((r>>1)&3).
// cp.async double-buffered over g in {0,1}; W frags one tap ahead.
// ---------------------------------------------------------------------------
extern __shared__ char smem[];

__global__ void __launch_bounds__(NTHR, 1)
conv_kernel(float* __restrict__ out) {
    const int t  = blockIdx.x;
    const int h0 = blockIdx.y * HH;
    const int b  = blockIdx.z;
    const int tid = threadIdx.x;
    const int wid = tid >> 5;
    const int lane = tid & 31;
    const int hrow = wid >> 1;      // 0..3
    const int mhalf = wid & 1;      // 0..1

    const unsigned sb = smem_u32(smem);

    float acc[2][6][4];
    #pragma unroll
    for (int mt = 0; mt < 2; mt++)
        #pragma unroll
        for (int nt = 0; nt < 6; nt++)
            #pragma unroll
            for (int k = 0; k < 4; k++) acc[mt][nt][k] = 0.f;

    // ldmatrix lane address components
    const int rb_off = (lane & 7) + ((lane >> 4) & 1) * 8;
    const int bhalf  = (lane >> 3) & 1;   // 16B half within a k16 (32B) span

    // ---- prefetch: fill buffer `buf` with group `g` slab (zfill halo) ----
    auto prefetch = [&](int g, int buf) {
        const char* xf8 = reinterpret_cast<const char*>(d_xf);
        #pragma unroll 1
        for (int i = tid; i < ROWS * 4; i += NTHR) {   // 3456 16B chunks
            const int r = i >> 2;
            const int c = i & 3;
            int t2 = r / (HP * WP);
            int rr = r - t2 * (HP * WP);
            int hp = rr / WP;
            int wp = rr - hp * WP;
            const int gt = t + t2 - 1, gh = h0 + hp - 1;
            const unsigned ok =
                (((unsigned)gt < (unsigned)T_) & ((unsigned)gh < (unsigned)H_))
                ? 16u : 0u;
            const int gtc = gt < 0 ? 0 : (gt >= T_ ? T_ - 1 : gt);
            const int ghc = gh < 0 ? 0 : (gh >= H_ ? H_ - 1 : gh);
            const size_t srow =
                ((((size_t)(b * 2 + g) * T_ + gtc) * H_ + ghc) * WP + wp);
            const char* src = xf8 + srow * 64 + c * 16;
            const unsigned dst = sb + buf * BUFB + r * 64 +
                                 ((c ^ ((r >> 1) & 3)) << 4);
            cp16(dst, src, ok);
        }
        cp_commit();
    };

    prefetch(0, 0);

    // W-fragment base: [b][g][tap][ks:2][mt:4][lane]; per-tap stride 256 uint4
    const uint4* wf0 = d_wfrag + (size_t)(b * 2) * 27 * 256 + lane;
    auto wptr = [&](int k) { return wf0 + (size_t)k * 256; };  // k = g*27+tap

    // preload W fragments for k=0 (this warp's 2 m-tiles, 2 ksteps)
    uint4 wc_[2][2];
    {
        const uint4* wt = wptr(0);
        #pragma unroll
        for (int ks = 0; ks < 2; ks++)
            #pragma unroll
            for (int mt = 0; mt < 2; mt++)
                wc_[ks][mt] = __ldg(wt + (ks * 4 + mhalf * 2 + mt) * 32);
    }

    #pragma unroll 1
    for (int g = 0; g < 2; g++) {
        cp_wait0();
        __syncthreads();
        if (g < 1) prefetch(g + 1, (g + 1) & 1);

        const unsigned sl = sb + (g & 1) * BUFB;

        #pragma unroll 1
        for (int tap = 0; tap < 27; tap++) {
            // ---- prefetch next tap's W fragments ----
            const int kf = g * 27 + tap;
            const uint4* wt = wptr(kf < 53 ? kf + 1 : 53);
            uint4 wn_[2][2];
            #pragma unroll
            for (int ks = 0; ks < 2; ks++)
                #pragma unroll
                for (int mt = 0; mt < 2; mt++)
                    wn_[ks][mt] = __ldg(wt + (ks * 4 + mhalf * 2 + mt) * 32);

            // ---- B fragments for current tap, both ksteps ----
            const int dt2 = tap / 9;
            const int rem = tap - dt2 * 9;
            const int dh  = rem / 3;
            const int dw  = rem - dh * 3;
            const int shift = (dt2 * HP + dh) * WP + dw;

            unsigned bf[2][12];
            #pragma unroll
            for (int ks = 0; ks < 2; ks++)
                #pragma unroll
                for (int q = 0; q < 3; q++) {
                    int r = hrow * 48 + q * 16 + rb_off + shift;
                    unsigned a = r * 64 +
                                 (((2 * ks + bhalf) ^ ((r >> 1) & 3)) << 4);
                    ldmx4(bf[ks][q * 4], bf[ks][q * 4 + 1],
                          bf[ks][q * 4 + 2], bf[ks][q * 4 + 3], sl + a);
                }

            // ---- 24 mmas: 2 ksteps x 2 mt x 6 nt ----
            #pragma unroll
            for (int ks = 0; ks < 2; ks++)
                #pragma unroll
                for (int mt = 0; mt < 2; mt++)
                    #pragma unroll
                    for (int nt = 0; nt < 6; nt++) {
                        const int q = nt >> 1, pr = (nt & 1) * 2;
                        mma_f16(acc[mt][nt], wc_[ks][mt],
                                bf[ks][q * 4 + pr], bf[ks][q * 4 + pr + 1]);
                    }

            // ---- rotate W pipeline ----
            #pragma unroll
            for (int ks = 0; ks < 2; ks++)
                #pragma unroll
                for (int mt = 0; mt < 2; mt++)
                    wc_[ks][mt] = wn_[ks][mt];
        }
    }

    // ---- epilogue: direct f32 store ----
    const int gh = h0 + hrow;
    #pragma unroll
    for (int mt = 0; mt < 2; mt++) {
        const int oc0 = mhalf * 32 + mt * 16 + (lane >> 2);
        #pragma unroll
        for (int nt = 0; nt < 6; nt++) {
            const int wc = nt * 8 + 2 * (lane & 3);
            if (wc < W_) {
                size_t o0 = ((size_t)(b * C_ + oc0) * T_ + t) * TH_STRIDE +
                            gh * W_ + wc;
                size_t o1 = o0 + (size_t)8 * SPAT;   // oc0+8
                *(float2*)(out + o0) = make_float2(acc[mt][nt][0], acc[mt][nt][1]);
                *(float2*)(out + o1) = make_float2(acc[mt][nt][2], acc[mt][nt][3]);
            }
        }
    }
}

// ---------------------------------------------------------------------------
extern "C" void kernel_launch(void* const* d_in, const int* in_sizes, int n_in,
                              void* d_out, int out_size) {
    const float* x        = (const float*)d_in[0];
    const float* w_reduce = (const float*)d_in[1];
    const float* b_reduce = (const float*)d_in[2];
    const float* w_fc1    = (const float*)d_in[3];
    const float* b_fc1    = (const float*)d_in[4];
    const float* w_fc2    = (const float*)d_in[5];
    float* out = (float*)d_out;

    cudaFuncSetAttribute(conv_kernel,
                         cudaFuncAttributeMaxDynamicSharedMemorySize, SM_TOTAL);

    gap_kernel<<<B_ * C_, 256>>>(x);
    fc_kernel<<<1, 256>>>(w_reduce, b_reduce, w_fc1, b_fc1);
    {
        const int total = B_ * 2 * 27 * 2 * 4 * 32;
        wdyn_kernel<<<(total + 255) / 256, 256>>>(w_fc2);
    }
    prepass_kernel<<<(PR2_ROWS + 255) / 256, 256>>>(x);
    {
        dim3 grid(T_, H_ / HH, B_);   // (30, 16, 16) = 7680 blocks
        conv_kernel<<<grid, NTHR, SM_TOTAL>>>(out);
    }
}